// round 2
// baseline (speedup 1.0000x reference)
#include <cuda_runtime.h>
#include <math.h>
#include <stdint.h>

// ---------------------------------------------------------------------------
// Problem constants (BidirectionalMamba): D=1024, E=2048, N=16, dt_rank=64,
// B=4, L=2048.  M = B*L = 8192 flattened rows.
// ---------------------------------------------------------------------------
#define D_MODEL  1024
#define E_DIM    2048
#define TWO_E    4096
#define N_ST     16
#define DT_RANK  64
#define PROJ_N   96            // dt_rank + 2N
#define B_SZ     4
#define L_SEQ    2048
#define M_ROWS   8192          // B_SZ * L_SEQ

// ---------------------------------------------------------------------------
// Scratch (device globals: allocation-free, graph-capture safe)
// ---------------------------------------------------------------------------
__device__ float g_xz[(size_t)M_ROWS * TWO_E];     // 134 MB  in-proj output (xi | z)
__device__ float g_xi[(size_t)M_ROWS * E_DIM];     // 67 MB   conv+silu output
__device__ float g_delta[(size_t)M_ROWS * E_DIM];  // 67 MB   softplus(dt@dt_w+dt_b)
__device__ float g_proj[(size_t)M_ROWS * PROJ_N];  // 3 MB    x-proj output (dt|B|C)
__device__ float g_y[(size_t)M_ROWS * E_DIM];      // 67 MB   scan output / gated y

// ---------------------------------------------------------------------------
// Generic fp32 SGEMM, C[M,N] = A[M,K] @ B[K,N], row-major.
// 128x128 tile, BK=8, 256 threads, 8x8 microtile.
// revA: read A rows time-reversed within each length-L_SEQ batch segment.
// revC: write C rows time-reversed.   accC: C += instead of C =.
// Handles N not a multiple of 128 (bounds on B loads / C stores).
// ---------------------------------------------------------------------------
#define BM 128
#define BN 128
#define BK 8

__global__ __launch_bounds__(256) void sgemm_kernel(
    const float* __restrict__ A, const float* __restrict__ Bm, float* __restrict__ C,
    int Mr, int Nc, int Kd, int revA, int revC, int accC)
{
    __shared__ float As[BK][BM + 4];
    __shared__ float Bs[BK][BN];

    const int tid = threadIdx.x;
    const int bx = blockIdx.x;      // N tiles
    const int by = blockIdx.y;      // M tiles

    const int arow = tid >> 1;            // 0..127
    const int acol = (tid & 1) << 2;      // 0 or 4
    const int brow = tid >> 5;            // 0..7
    const int bcol = (tid & 31) << 2;     // 0..124

    const int tx = tid & 15;
    const int ty = tid >> 4;

    float acc[8][8];
#pragma unroll
    for (int i = 0; i < 8; i++)
#pragma unroll
        for (int j = 0; j < 8; j++) acc[i][j] = 0.f;

    int growA = by * BM + arow;
    if (revA) growA = (growA & ~(L_SEQ - 1)) | (L_SEQ - 1 - (growA & (L_SEQ - 1)));
    const float* Aptr = A + (size_t)growA * Kd + acol;

    const int gcol = bx * BN + bcol;
    const bool bok = (gcol + 3 < Nc);

    for (int k0 = 0; k0 < Kd; k0 += BK) {
        float4 a4 = *(const float4*)(Aptr + k0);
        As[acol + 0][arow] = a4.x;
        As[acol + 1][arow] = a4.y;
        As[acol + 2][arow] = a4.z;
        As[acol + 3][arow] = a4.w;

        float4 b4 = make_float4(0.f, 0.f, 0.f, 0.f);
        if (bok) b4 = *(const float4*)(Bm + (size_t)(k0 + brow) * Nc + gcol);
        *(float4*)&Bs[brow][bcol] = b4;

        __syncthreads();

#pragma unroll
        for (int kk = 0; kk < BK; kk++) {
            float4 a0 = *(const float4*)&As[kk][ty * 8];
            float4 a1 = *(const float4*)&As[kk][ty * 8 + 4];
            float4 b0 = *(const float4*)&Bs[kk][tx * 8];
            float4 b1 = *(const float4*)&Bs[kk][tx * 8 + 4];
            float ra[8] = {a0.x, a0.y, a0.z, a0.w, a1.x, a1.y, a1.z, a1.w};
            float rb[8] = {b0.x, b0.y, b0.z, b0.w, b1.x, b1.y, b1.z, b1.w};
#pragma unroll
            for (int i = 0; i < 8; i++)
#pragma unroll
                for (int j = 0; j < 8; j++)
                    acc[i][j] = fmaf(ra[i], rb[j], acc[i][j]);
        }
        __syncthreads();
    }

#pragma unroll
    for (int i = 0; i < 8; i++) {
        int gr = by * BM + ty * 8 + i;
        if (revC) gr = (gr & ~(L_SEQ - 1)) | (L_SEQ - 1 - (gr & (L_SEQ - 1)));
#pragma unroll
        for (int j = 0; j < 8; j += 4) {
            int gc = bx * BN + tx * 8 + j;
            if (gc + 3 < Nc) {
                float4* cp = (float4*)(C + (size_t)gr * Nc + gc);
                float4 v = make_float4(acc[i][j], acc[i][j + 1], acc[i][j + 2], acc[i][j + 3]);
                if (accC) {
                    float4 o = *cp;
                    v.x += o.x; v.y += o.y; v.z += o.z; v.w += o.w;
                }
                *cp = v;
            }
        }
    }
}

// ---------------------------------------------------------------------------
// Depthwise causal conv1d (D_CONV=4) + SiLU over the xi half of g_xz.
// out g_xi[m, e] = silu( conv_b[e] + sum_k xz[m-3+k, e] * conv_w[e,k] )
// ---------------------------------------------------------------------------
__global__ __launch_bounds__(256) void conv_silu_kernel(
    const float* __restrict__ conv_w, const float* __restrict__ conv_b)
{
    size_t idx = (size_t)blockIdx.x * blockDim.x + threadIdx.x;
    if (idx >= (size_t)M_ROWS * E_DIM) return;
    int e = (int)(idx & (E_DIM - 1));
    int m = (int)(idx >> 11);
    int l = m & (L_SEQ - 1);

    float acc = conv_b[e];
#pragma unroll
    for (int kk = 0; kk < 4; kk++) {
        int ll = l - 3 + kk;
        if (ll >= 0)
            acc = fmaf(g_xz[(size_t)(m - 3 + kk) * TWO_E + e], conv_w[e * 4 + kk], acc);
    }
    g_xi[idx] = acc / (1.f + __expf(-acc));     // silu
}

// ---------------------------------------------------------------------------
// delta = softplus( proj[:, :64] @ dt_w + dt_b ).  K=64 resident in smem,
// each thread produces 4 adjacent e outputs (float4 loads of dt_w row).
// grid: (E/1024, M_ROWS), block 256.
// ---------------------------------------------------------------------------
__device__ __forceinline__ float softplusf(float x)
{
    return (x > 20.f) ? x : log1pf(__expf(x));
}

__global__ __launch_bounds__(256) void delta_kernel(
    const float* __restrict__ dt_w, const float* __restrict__ dt_b)
{
    __shared__ float s[DT_RANK];
    const int m = blockIdx.y;
    const int e = (blockIdx.x * 256 + threadIdx.x) * 4;
    if (threadIdx.x < DT_RANK) s[threadIdx.x] = g_proj[(size_t)m * PROJ_N + threadIdx.x];
    __syncthreads();

    float4 acc = *(const float4*)(dt_b + e);
#pragma unroll 8
    for (int r = 0; r < DT_RANK; r++) {
        float4 w = *(const float4*)(dt_w + (size_t)r * E_DIM + e);
        float sv = s[r];
        acc.x = fmaf(sv, w.x, acc.x);
        acc.y = fmaf(sv, w.y, acc.y);
        acc.z = fmaf(sv, w.z, acc.z);
        acc.w = fmaf(sv, w.w, acc.w);
    }
    float4 o;
    o.x = softplusf(acc.x);
    o.y = softplusf(acc.y);
    o.z = softplusf(acc.z);
    o.w = softplusf(acc.w);
    *(float4*)(g_delta + (size_t)m * E_DIM + e) = o;
}

// ---------------------------------------------------------------------------
// Selective scan.  One chain = (b, e); 16 lanes per chain (lane = state n),
// 2 chains per warp.  h_n <- exp(delta*A_n)*h_n + delta*u*B_n ; y = sum h_n*C_n.
//
// Fast path (data-verified per chain): if A[e,n] == k_n * A[e,0] with integer
// k_n in [1,16], then decay_n = p^{k_n}, p = exp(delta*A0) -> 1 MUFU per step
// instead of 16.  Falls back to direct expf otherwise.
// Next-step operands are prefetched so the only loop-carried dep is one FMA.
// ---------------------------------------------------------------------------
__global__ __launch_bounds__(256) void scan_kernel(const float* __restrict__ A_log)
{
    const int lane = threadIdx.x & 31;
    const int w = blockIdx.x * (blockDim.x >> 5) + (threadIdx.x >> 5);
    const int half = lane >> 4;
    const int n = lane & 15;
    const int chain = 2 * w + half;          // 0 .. B*E-1
    const int b = chain >> 11;               // chain / E
    const int e = chain & (E_DIM - 1);

    const float a = -__expf(A_log[e * N_ST + n]);      // A[e,n] (negative)
    const float a0 = __shfl_sync(0xffffffffu, a, lane & 16);
    const float kf = rintf(a / a0);
    const int k = (int)kf;
    const bool ok = (fabsf(a - kf * a0) <= 1e-5f * fmaxf(fabsf(a), 1e-20f)) &&
                    (k >= 1) && (k <= 16);
    const bool fast = __all_sync(0xffffffffu, ok);

    const float* dp = g_delta + (size_t)b * L_SEQ * E_DIM + e;
    const float* up = g_xi    + (size_t)b * L_SEQ * E_DIM + e;
    const float* pp = g_proj  + (size_t)b * L_SEQ * PROJ_N;
    float*       yp = g_y     + (size_t)b * L_SEQ * E_DIM + e;

    float h = 0.f;
    float d  = dp[0];
    float u  = up[0];
    float Bv = pp[64 + n];
    float Cv = pp[80 + n];

    for (int l = 0; l < L_SEQ; l++) {
        float dn = 0.f, un = 0.f, Bn = 0.f, Cn = 0.f;
        if (l + 1 < L_SEQ) {
            dn = dp[(size_t)(l + 1) * E_DIM];
            un = up[(size_t)(l + 1) * E_DIM];
            Bn = pp[(l + 1) * PROJ_N + 64 + n];
            Cn = pp[(l + 1) * PROJ_N + 80 + n];
        }

        float decay;
        if (fast) {
            float p = __expf(d * a0);
            float p2 = p * p, p4 = p2 * p2, p8 = p4 * p4;
            decay = 1.f;
            if (k & 1)  decay *= p;
            if (k & 2)  decay *= p2;
            if (k & 4)  decay *= p4;
            if (k & 8)  decay *= p8;
            if (k & 16) decay *= p8 * p8;
        } else {
            decay = __expf(d * a);
        }

        h = fmaf(decay, h, d * u * Bv);

        float v = h * Cv;
        v += __shfl_xor_sync(0xffffffffu, v, 1);
        v += __shfl_xor_sync(0xffffffffu, v, 2);
        v += __shfl_xor_sync(0xffffffffu, v, 4);
        v += __shfl_xor_sync(0xffffffffu, v, 8);
        if (n == 0) yp[(size_t)l * E_DIM] = v;

        d = dn; u = un; Bv = Bn; Cv = Cn;
    }
}

// ---------------------------------------------------------------------------
// y = (y_scan + xi * Dp) * silu(z),  z = xz[:, E:2E]
// ---------------------------------------------------------------------------
__global__ __launch_bounds__(256) void combine_kernel(const float* __restrict__ Dp)
{
    size_t idx = (size_t)blockIdx.x * blockDim.x + threadIdx.x;
    if (idx >= (size_t)M_ROWS * E_DIM) return;
    int e = (int)(idx & (E_DIM - 1));
    size_t m = idx >> 11;
    float z = g_xz[m * TWO_E + E_DIM + e];
    float sz = z / (1.f + __expf(-z));
    g_y[idx] = (g_y[idx] + g_xi[idx] * Dp[e]) * sz;
}

// ---------------------------------------------------------------------------
// Launcher: runs fwd then bwd direction (bwd = time-reversed rows folded into
// the in-proj read and out-proj write; out-proj of bwd accumulates into d_out).
// ---------------------------------------------------------------------------
extern "C" void kernel_launch(void* const* d_in, const int* in_sizes, int n_in,
                              void* d_out, int out_size)
{
    (void)in_sizes; (void)n_in; (void)out_size;
    const float* x = (const float*)d_in[0];
    float* out = (float*)d_out;

    float *p_xz, *p_xi, *p_proj, *p_y;
    cudaGetSymbolAddress((void**)&p_xz, g_xz);
    cudaGetSymbolAddress((void**)&p_xi, g_xi);
    cudaGetSymbolAddress((void**)&p_proj, g_proj);
    cudaGetSymbolAddress((void**)&p_y, g_y);

    const size_t elems_e = (size_t)M_ROWS * E_DIM;
    const int blocks_e = (int)((elems_e + 255) / 256);

    for (int dir = 0; dir < 2; dir++) {
        const float* in_w    = (const float*)d_in[1 + dir * 9 + 0];
        const float* conv_w  = (const float*)d_in[1 + dir * 9 + 1];
        const float* conv_b  = (const float*)d_in[1 + dir * 9 + 2];
        const float* xproj_w = (const float*)d_in[1 + dir * 9 + 3];
        const float* dt_w    = (const float*)d_in[1 + dir * 9 + 4];
        const float* dt_b    = (const float*)d_in[1 + dir * 9 + 5];
        const float* A_log   = (const float*)d_in[1 + dir * 9 + 6];
        const float* Dp      = (const float*)d_in[1 + dir * 9 + 7];
        const float* out_w   = (const float*)d_in[1 + dir * 9 + 8];

        // 1) xz = x @ in_w          (rows of x read reversed for bwd)
        dim3 g1(TWO_E / BN, M_ROWS / BM);
        sgemm_kernel<<<g1, 256>>>(x, in_w, p_xz, M_ROWS, TWO_E, D_MODEL, dir, 0, 0);

        // 2) xi = silu(causal_conv(xz[:, :E]))
        conv_silu_kernel<<<blocks_e, 256>>>(conv_w, conv_b);

        // 3) proj = xi @ xproj_w    (N=96, bounds-guarded tile)
        dim3 g2(1, M_ROWS / BM);
        sgemm_kernel<<<g2, 256>>>(p_xi, xproj_w, p_proj, M_ROWS, PROJ_N, E_DIM, 0, 0, 0);

        // 4) delta = softplus(proj[:, :64] @ dt_w + dt_b)
        dim3 g3(E_DIM / 1024, M_ROWS);
        delta_kernel<<<g3, 256>>>(dt_w, dt_b);

        // 5) selective scan -> g_y
        scan_kernel<<<512, 256>>>(A_log);

        // 6) y = (y + xi*Dp) * silu(z)
        combine_kernel<<<blocks_e, 256>>>(Dp);

        // 7) out (+)= y @ out_w     (rows written reversed + accumulated for bwd)
        dim3 g4(D_MODEL / BN, M_ROWS / BM);
        sgemm_kernel<<<g4, 256>>>(p_y, out_w, out, M_ROWS, D_MODEL, E_DIM, 0, dir, dir);
    }
}

// round 3
// speedup vs baseline: 1.1086x; 1.1086x over previous
#include <cuda_runtime.h>
#include <math.h>
#include <stdint.h>

// ---------------------------------------------------------------------------
// BidirectionalMamba: D=1024, E=2048, N=16, dt_rank=64, B=4, L=2048.
// ---------------------------------------------------------------------------
#define D_MODEL  1024
#define E_DIM    2048
#define TWO_E    4096
#define N_ST     16
#define DT_RANK  64
#define PROJ_N   96
#define B_SZ     4
#define L_SEQ    2048
#define M_ROWS   8192

// Scratch (device globals: allocation-free, graph-capture safe)
__device__ float g_xz[(size_t)M_ROWS * TWO_E];
__device__ float g_xi[(size_t)M_ROWS * E_DIM];
__device__ float g_delta[(size_t)M_ROWS * E_DIM];
__device__ float g_proj[(size_t)M_ROWS * PROJ_N];
__device__ float g_y[(size_t)M_ROWS * E_DIM];

// ---------------------------------------------------------------------------
// TF32 helpers
// ---------------------------------------------------------------------------
__device__ __forceinline__ uint32_t f2tf32(float f)
{
    uint32_t u;
    asm("cvt.rna.tf32.f32 %0, %1;" : "=r"(u) : "f"(f));
    return u;
}

// split v into tf32 hi + tf32 lo (lo = exact residual, re-rounded)
__device__ __forceinline__ void tf32_split(float v, uint32_t& hi, uint32_t& lo)
{
    hi = f2tf32(v);
    float r = v - __uint_as_float(hi);
    lo = f2tf32(r);
}

__device__ __forceinline__ void mma_tf32(float* d, const uint32_t* a, const uint32_t* b)
{
    asm volatile(
        "mma.sync.aligned.m16n8k8.row.col.f32.tf32.tf32.f32 "
        "{%0,%1,%2,%3}, {%4,%5,%6,%7}, {%8,%9}, {%0,%1,%2,%3};\n"
        : "+f"(d[0]), "+f"(d[1]), "+f"(d[2]), "+f"(d[3])
        : "r"(a[0]), "r"(a[1]), "r"(a[2]), "r"(a[3]), "r"(b[0]), "r"(b[1]));
}

// ---------------------------------------------------------------------------
// TF32 tensor-core GEMM with 3-term precision split (~fp32 accuracy).
// C[M,N] = A[M,K] @ B[K,N], row-major.  Block tile 128x128, BK=32,
// 8 warps, warp tile 64x32, 4x4 m16n8k8 mma tiles per warp.
// revA: read A rows time-reversed within each L_SEQ segment.
// revC: write C rows reversed.  accC: C += .  N guarded (handles N=96).
// ---------------------------------------------------------------------------
#define ASTRIDE 36
#define BSTRIDE 132

__global__ __launch_bounds__(256) void mma_gemm_kernel(
    const float* __restrict__ A, const float* __restrict__ Bm, float* __restrict__ C,
    int Mr, int Nc, int Kd, int revA, int revC, int accC)
{
    __shared__ float As[128][ASTRIDE];
    __shared__ float Bs[32][BSTRIDE];

    const int tid  = threadIdx.x;
    const int lane = tid & 31;
    const int warp = tid >> 5;
    const int wm   = warp & 1;          // 2 warp-rows
    const int wn   = warp >> 1;         // 4 warp-cols
    const int g    = lane >> 2;         // groupID 0..7
    const int tg   = lane & 3;          // thread-in-group 0..3

    const int bx = blockIdx.x;
    const int by = blockIdx.y;

    float acc[4][4][4];
#pragma unroll
    for (int i = 0; i < 4; i++)
#pragma unroll
        for (int j = 0; j < 4; j++)
#pragma unroll
            for (int r = 0; r < 4; r++) acc[i][j][r] = 0.f;

    // global->smem mapping
    const int a_col = (tid & 7) * 4;         // 0..28
    const int a_row0 = tid >> 3;             // 0..31
    const int b_col = (tid & 31) * 4;        // 0..124
    const int b_row0 = tid >> 5;             // 0..7
    const int b_gcol = bx * 128 + b_col;
    const bool b_ok = (b_gcol + 3 < Nc) || (b_gcol + 3 < Nc + 0); // simple guard
    const bool bok = (b_gcol + 3 < Nc);

    // A row pointers (4 rows per thread, stride 32)
    const float* aptr[4];
#pragma unroll
    for (int p = 0; p < 4; p++) {
        int r = by * 128 + a_row0 + 32 * p;
        if (revA) r = (r & ~(L_SEQ - 1)) | (L_SEQ - 1 - (r & (L_SEQ - 1)));
        aptr[p] = A + (size_t)r * Kd + a_col;
    }

    for (int k0 = 0; k0 < Kd; k0 += 32) {
#pragma unroll
        for (int p = 0; p < 4; p++) {
            float4 v = *(const float4*)(aptr[p] + k0);
            *(float4*)&As[a_row0 + 32 * p][a_col] = v;
        }
#pragma unroll
        for (int p = 0; p < 4; p++) {
            float4 v = make_float4(0.f, 0.f, 0.f, 0.f);
            if (bok) v = *(const float4*)(Bm + (size_t)(k0 + b_row0 + 8 * p) * Nc + b_gcol);
            *(float4*)&Bs[b_row0 + 8 * p][b_col] = v;
        }
        __syncthreads();

#pragma unroll
        for (int ks = 0; ks < 4; ks++) {
            const int k8 = ks * 8;
            uint32_t ahi[4][4], alo[4][4];
#pragma unroll
            for (int mt = 0; mt < 4; mt++) {
                const int rb = wm * 64 + mt * 16;
                float a0 = As[rb + g][k8 + tg];
                float a1 = As[rb + g + 8][k8 + tg];
                float a2 = As[rb + g][k8 + tg + 4];
                float a3 = As[rb + g + 8][k8 + tg + 4];
                tf32_split(a0, ahi[mt][0], alo[mt][0]);
                tf32_split(a1, ahi[mt][1], alo[mt][1]);
                tf32_split(a2, ahi[mt][2], alo[mt][2]);
                tf32_split(a3, ahi[mt][3], alo[mt][3]);
            }
            uint32_t bhi[4][2], blo[4][2];
#pragma unroll
            for (int nt = 0; nt < 4; nt++) {
                const int cb = wn * 32 + nt * 8;
                float b0 = Bs[k8 + tg][cb + g];
                float b1 = Bs[k8 + tg + 4][cb + g];
                tf32_split(b0, bhi[nt][0], blo[nt][0]);
                tf32_split(b1, bhi[nt][1], blo[nt][1]);
            }
#pragma unroll
            for (int mt = 0; mt < 4; mt++)
#pragma unroll
                for (int nt = 0; nt < 4; nt++) {
                    mma_tf32(acc[mt][nt], ahi[mt], bhi[nt]);
                    mma_tf32(acc[mt][nt], alo[mt], bhi[nt]);
                    mma_tf32(acc[mt][nt], ahi[mt], blo[nt]);
                }
        }
        __syncthreads();
    }

    // epilogue
#pragma unroll
    for (int mt = 0; mt < 4; mt++) {
#pragma unroll
        for (int half = 0; half < 2; half++) {
            int gr = by * 128 + wm * 64 + mt * 16 + g + half * 8;
            if (revC) gr = (gr & ~(L_SEQ - 1)) | (L_SEQ - 1 - (gr & (L_SEQ - 1)));
            float* crow = C + (size_t)gr * Nc;
#pragma unroll
            for (int nt = 0; nt < 4; nt++) {
                int gc = bx * 128 + wn * 32 + nt * 8 + tg * 2;
                float v0 = acc[mt][nt][half * 2 + 0];
                float v1 = acc[mt][nt][half * 2 + 1];
                if (gc + 1 < Nc) {
                    if (accC) { v0 += crow[gc]; v1 += crow[gc + 1]; }
                    crow[gc] = v0;
                    crow[gc + 1] = v1;
                }
            }
        }
    }
}

// ---------------------------------------------------------------------------
// Depthwise causal conv1d (D_CONV=4) + SiLU over the xi half of g_xz.
// ---------------------------------------------------------------------------
__global__ __launch_bounds__(256) void conv_silu_kernel(
    const float* __restrict__ conv_w, const float* __restrict__ conv_b)
{
    size_t idx = (size_t)blockIdx.x * blockDim.x + threadIdx.x;
    if (idx >= (size_t)M_ROWS * E_DIM) return;
    int e = (int)(idx & (E_DIM - 1));
    int m = (int)(idx >> 11);
    int l = m & (L_SEQ - 1);

    float acc = conv_b[e];
#pragma unroll
    for (int kk = 0; kk < 4; kk++) {
        int ll = l - 3 + kk;
        if (ll >= 0)
            acc = fmaf(g_xz[(size_t)(m - 3 + kk) * TWO_E + e], conv_w[e * 4 + kk], acc);
    }
    g_xi[idx] = acc / (1.f + __expf(-acc));
}

// ---------------------------------------------------------------------------
// delta = softplus( proj[:, :64] @ dt_w + dt_b )
// ---------------------------------------------------------------------------
__device__ __forceinline__ float softplusf(float x)
{
    return (x > 20.f) ? x : log1pf(__expf(x));
}

__global__ __launch_bounds__(256) void delta_kernel(
    const float* __restrict__ dt_w, const float* __restrict__ dt_b)
{
    __shared__ float s[DT_RANK];
    const int m = blockIdx.y;
    const int e = (blockIdx.x * 256 + threadIdx.x) * 4;
    if (threadIdx.x < DT_RANK) s[threadIdx.x] = g_proj[(size_t)m * PROJ_N + threadIdx.x];
    __syncthreads();

    float4 acc = *(const float4*)(dt_b + e);
#pragma unroll 8
    for (int r = 0; r < DT_RANK; r++) {
        float4 w = *(const float4*)(dt_w + (size_t)r * E_DIM + e);
        float sv = s[r];
        acc.x = fmaf(sv, w.x, acc.x);
        acc.y = fmaf(sv, w.y, acc.y);
        acc.z = fmaf(sv, w.z, acc.z);
        acc.w = fmaf(sv, w.w, acc.w);
    }
    float4 o;
    o.x = softplusf(acc.x);
    o.y = softplusf(acc.y);
    o.z = softplusf(acc.z);
    o.w = softplusf(acc.w);
    *(float4*)(g_delta + (size_t)m * E_DIM + e) = o;
}

// ---------------------------------------------------------------------------
// Selective scan: 16 lanes per chain (lane = state n), 2 chains/warp.
// Fast path: A[e,n] = k_n * A[e,0], integer k_n -> 1 exp/step instead of 16.
// ---------------------------------------------------------------------------
__global__ __launch_bounds__(256) void scan_kernel(const float* __restrict__ A_log)
{
    const int lane = threadIdx.x & 31;
    const int w = blockIdx.x * (blockDim.x >> 5) + (threadIdx.x >> 5);
    const int half = lane >> 4;
    const int n = lane & 15;
    const int chain = 2 * w + half;
    const int b = chain >> 11;
    const int e = chain & (E_DIM - 1);

    const float a = -__expf(A_log[e * N_ST + n]);
    const float a0 = __shfl_sync(0xffffffffu, a, lane & 16);
    const float kf = rintf(a / a0);
    const int k = (int)kf;
    const bool ok = (fabsf(a - kf * a0) <= 1e-5f * fmaxf(fabsf(a), 1e-20f)) &&
                    (k >= 1) && (k <= 16);
    const bool fast = __all_sync(0xffffffffu, ok);

    const float* dp = g_delta + (size_t)b * L_SEQ * E_DIM + e;
    const float* up = g_xi    + (size_t)b * L_SEQ * E_DIM + e;
    const float* pp = g_proj  + (size_t)b * L_SEQ * PROJ_N;
    float*       yp = g_y     + (size_t)b * L_SEQ * E_DIM + e;

    float h = 0.f;
    float d  = dp[0];
    float u  = up[0];
    float Bv = pp[64 + n];
    float Cv = pp[80 + n];

    for (int l = 0; l < L_SEQ; l++) {
        float dn = 0.f, un = 0.f, Bn = 0.f, Cn = 0.f;
        if (l + 1 < L_SEQ) {
            dn = dp[(size_t)(l + 1) * E_DIM];
            un = up[(size_t)(l + 1) * E_DIM];
            Bn = pp[(l + 1) * PROJ_N + 64 + n];
            Cn = pp[(l + 1) * PROJ_N + 80 + n];
        }

        float decay;
        if (fast) {
            float p = __expf(d * a0);
            float p2 = p * p, p4 = p2 * p2, p8 = p4 * p4;
            decay = 1.f;
            if (k & 1)  decay *= p;
            if (k & 2)  decay *= p2;
            if (k & 4)  decay *= p4;
            if (k & 8)  decay *= p8;
            if (k & 16) decay *= p8 * p8;
        } else {
            decay = __expf(d * a);
        }

        h = fmaf(decay, h, d * u * Bv);

        float v = h * Cv;
        v += __shfl_xor_sync(0xffffffffu, v, 1);
        v += __shfl_xor_sync(0xffffffffu, v, 2);
        v += __shfl_xor_sync(0xffffffffu, v, 4);
        v += __shfl_xor_sync(0xffffffffu, v, 8);
        if (n == 0) yp[(size_t)l * E_DIM] = v;

        d = dn; u = un; Bv = Bn; Cv = Cn;
    }
}

// ---------------------------------------------------------------------------
// y = (y_scan + xi * Dp) * silu(z)
// ---------------------------------------------------------------------------
__global__ __launch_bounds__(256) void combine_kernel(const float* __restrict__ Dp)
{
    size_t idx = (size_t)blockIdx.x * blockDim.x + threadIdx.x;
    if (idx >= (size_t)M_ROWS * E_DIM) return;
    int e = (int)(idx & (E_DIM - 1));
    size_t m = idx >> 11;
    float z = g_xz[m * TWO_E + E_DIM + e];
    float sz = z / (1.f + __expf(-z));
    g_y[idx] = (g_y[idx] + g_xi[idx] * Dp[e]) * sz;
}

// ---------------------------------------------------------------------------
// Launcher
// ---------------------------------------------------------------------------
extern "C" void kernel_launch(void* const* d_in, const int* in_sizes, int n_in,
                              void* d_out, int out_size)
{
    (void)in_sizes; (void)n_in; (void)out_size;
    const float* x = (const float*)d_in[0];
    float* out = (float*)d_out;

    float *p_xz, *p_xi, *p_proj, *p_y;
    cudaGetSymbolAddress((void**)&p_xz, g_xz);
    cudaGetSymbolAddress((void**)&p_xi, g_xi);
    cudaGetSymbolAddress((void**)&p_proj, g_proj);
    cudaGetSymbolAddress((void**)&p_y, g_y);

    const size_t elems_e = (size_t)M_ROWS * E_DIM;
    const int blocks_e = (int)((elems_e + 255) / 256);

    for (int dir = 0; dir < 2; dir++) {
        const float* in_w    = (const float*)d_in[1 + dir * 9 + 0];
        const float* conv_w  = (const float*)d_in[1 + dir * 9 + 1];
        const float* conv_b  = (const float*)d_in[1 + dir * 9 + 2];
        const float* xproj_w = (const float*)d_in[1 + dir * 9 + 3];
        const float* dt_w    = (const float*)d_in[1 + dir * 9 + 4];
        const float* dt_b    = (const float*)d_in[1 + dir * 9 + 5];
        const float* A_log   = (const float*)d_in[1 + dir * 9 + 6];
        const float* Dp      = (const float*)d_in[1 + dir * 9 + 7];
        const float* out_w   = (const float*)d_in[1 + dir * 9 + 8];

        // 1) xz = x @ in_w   (rows of x read reversed for bwd)
        dim3 g1(TWO_E / 128, M_ROWS / 128);
        mma_gemm_kernel<<<g1, 256>>>(x, in_w, p_xz, M_ROWS, TWO_E, D_MODEL, dir, 0, 0);

        // 2) xi = silu(causal_conv(xz[:, :E]))
        conv_silu_kernel<<<blocks_e, 256>>>(conv_w, conv_b);

        // 3) proj = xi @ xproj_w  (N=96, guarded)
        dim3 g2(1, M_ROWS / 128);
        mma_gemm_kernel<<<g2, 256>>>(p_xi, xproj_w, p_proj, M_ROWS, PROJ_N, E_DIM, 0, 0, 0);

        // 4) delta = softplus(proj[:, :64] @ dt_w + dt_b)
        dim3 g3(E_DIM / 1024, M_ROWS);
        delta_kernel<<<g3, 256>>>(dt_w, dt_b);

        // 5) selective scan -> g_y
        scan_kernel<<<512, 256>>>(A_log);

        // 6) y = (y + xi*Dp) * silu(z)
        combine_kernel<<<blocks_e, 256>>>(Dp);

        // 7) out (+)= y @ out_w  (rows reversed + accumulate for bwd)
        dim3 g4(D_MODEL / 128, M_ROWS / 128);
        mma_gemm_kernel<<<g4, 256>>>(p_y, out_w, out, M_ROWS, D_MODEL, E_DIM, 0, dir, dir);
    }
}

// round 5
// speedup vs baseline: 1.6765x; 1.5122x over previous
#include <cuda_runtime.h>
#include <cuda_fp16.h>
#include <math.h>
#include <stdint.h>

// ---------------------------------------------------------------------------
// BidirectionalMamba: D=1024, E=2048, N=16, dt_rank=64, B=4, L=2048.
// ---------------------------------------------------------------------------
#define D_MODEL  1024
#define E_DIM    2048
#define TWO_E    4096
#define N_ST     16
#define DT_RANK  64
#define PROJ_N   96
#define B_SZ     4
#define L_SEQ    2048
#define M_ROWS   8192

// ---------------------------------------------------------------------------
// Scratch (device globals: allocation-free, graph-capture safe)
// ---------------------------------------------------------------------------
__device__ float g_xz[(size_t)M_ROWS * TWO_E];
__device__ float g_xi[(size_t)M_ROWS * E_DIM];
__device__ float g_delta[(size_t)M_ROWS * E_DIM];
__device__ float g_proj[(size_t)M_ROWS * PROJ_N];
__device__ float g_y[(size_t)M_ROWS * E_DIM];

// fp16 split planes (A operands, row-major [M,K])
__device__ __half g_xhi[(size_t)M_ROWS * D_MODEL];
__device__ __half g_xlo[(size_t)M_ROWS * D_MODEL];
__device__ __half g_xihi[(size_t)M_ROWS * E_DIM];
__device__ __half g_xilo[(size_t)M_ROWS * E_DIM];
__device__ __half g_yhi[(size_t)M_ROWS * E_DIM];
__device__ __half g_ylo[(size_t)M_ROWS * E_DIM];
// transposed weight planes W^T [Npad, K]
__device__ __half g_btin_hi[(size_t)TWO_E * D_MODEL];
__device__ __half g_btin_lo[(size_t)TWO_E * D_MODEL];
__device__ __half g_btxp_hi[(size_t)128 * E_DIM];
__device__ __half g_btxp_lo[(size_t)128 * E_DIM];
__device__ __half g_btout_hi[(size_t)D_MODEL * E_DIM];
__device__ __half g_btout_lo[(size_t)D_MODEL * E_DIM];

// ---------------------------------------------------------------------------
// helpers
// ---------------------------------------------------------------------------
__device__ __forceinline__ uint32_t smem_to_u32(const void* p)
{
    uint32_t a;
    asm("{ .reg .u64 t; cvta.to.shared.u64 t, %1; cvt.u32.u64 %0, t; }" : "=r"(a) : "l"(p));
    return a;
}

#define LDSM_X4(r, a) \
    asm volatile("ldmatrix.sync.aligned.m8n8.x4.shared.b16 {%0,%1,%2,%3}, [%4];" \
        : "=r"((r)[0]), "=r"((r)[1]), "=r"((r)[2]), "=r"((r)[3]) : "r"(a))

__device__ __forceinline__ void mma16816(float* d, const uint32_t* a, const uint32_t* b)
{
    asm volatile(
        "mma.sync.aligned.m16n8k16.row.col.f32.f16.f16.f32 "
        "{%0,%1,%2,%3}, {%4,%5,%6,%7}, {%8,%9}, {%0,%1,%2,%3};"
        : "+f"(d[0]), "+f"(d[1]), "+f"(d[2]), "+f"(d[3])
        : "r"(a[0]), "r"(a[1]), "r"(a[2]), "r"(a[3]), "r"(b[0]), "r"(b[1]));
}

#define CP_ASYNC16(dst, src) \
    asm volatile("cp.async.cg.shared.global [%0], [%1], 16;" :: "r"(dst), "l"(src))
#define CP_COMMIT()  asm volatile("cp.async.commit_group;" ::: "memory")
#define CP_WAIT(n)   asm volatile("cp.async.wait_group %0;" :: "n"(n) : "memory")

// ---------------------------------------------------------------------------
// Split-fp16 HMMA GEMM: C[M,N] = A[M,K] @ W[K,N]  (B planes hold W^T [N,K]).
// Block tile 128x128, BK=32, 256 threads (8 warps, 2x4), warp tile 64x32.
// Double-buffered cp.async stages.  3-term split: hihi + lohi + hilo.
// revC: write rows time-reversed per L_SEQ segment;  accC: C += .
// ---------------------------------------------------------------------------
#define ASTR_B      80                      // padded row pitch in bytes (32 halves + 8 pad)
#define PLANE_B     (128 * ASTR_B)          // 10240 bytes per plane tile
#define STAGE_B     (4 * PLANE_B)           // 40960 bytes per stage
#define GEMM_SMEM   (2 * STAGE_B)           // 81920

__device__ __forceinline__ void ld_plane(
    const __half* __restrict__ gsrc, int row0, int K, int k0, char* stp, int tid)
{
#pragma unroll
    for (int j = 0; j < 2; j++) {
        int cid = j * 256 + tid;            // 0..511
        int r = cid >> 2;
        int c = cid & 3;
        const void* src = gsrc + (size_t)(row0 + r) * K + k0 + c * 8;
        uint32_t dst = smem_to_u32(stp + r * ASTR_B + c * 16);
        CP_ASYNC16(dst, src);
    }
}

__global__ __launch_bounds__(256) void hmma_gemm(
    const __half* __restrict__ Ahi, const __half* __restrict__ Alo,
    const __half* __restrict__ Bhi, const __half* __restrict__ Blo,
    float* __restrict__ C, int K, int Nc, int revC, int accC)
{
    extern __shared__ char smem[];
    const int tid  = threadIdx.x;
    const int lane = tid & 31;
    const int warp = tid >> 5;
    const int wm   = warp & 1;
    const int wn   = warp >> 1;
    const int g    = lane >> 2;
    const int tg   = lane & 3;
    const int bx = blockIdx.x;
    const int by = blockIdx.y;
    const int rowA = by * 128;
    const int rowB = bx * 128;

    float acc[4][4][4];
#pragma unroll
    for (int i = 0; i < 4; i++)
#pragma unroll
        for (int j = 0; j < 4; j++)
#pragma unroll
            for (int r = 0; r < 4; r++) acc[i][j][r] = 0.f;

    // per-lane ldmatrix offsets
    const int a_r = lane & 15;
    const int a_c = (lane >> 4) * 16;                       // bytes
    const int b_r = (lane & 7) + (((lane >> 4) & 1) << 3);
    const int b_c = ((lane >> 3) & 1) * 16;                 // bytes

    const int T = K >> 5;

    // prologue
    {
        char* st = smem;
        ld_plane(Ahi, rowA, K, 0, st + 0 * PLANE_B, tid);
        ld_plane(Alo, rowA, K, 0, st + 1 * PLANE_B, tid);
        ld_plane(Bhi, rowB, K, 0, st + 2 * PLANE_B, tid);
        ld_plane(Blo, rowB, K, 0, st + 3 * PLANE_B, tid);
        CP_COMMIT();
    }

    for (int t = 0; t < T; t++) {
        const int cur = t & 1;
        if (t + 1 < T) {
            char* st = smem + (cur ^ 1) * STAGE_B;
            const int k0 = (t + 1) << 5;
            ld_plane(Ahi, rowA, K, k0, st + 0 * PLANE_B, tid);
            ld_plane(Alo, rowA, K, k0, st + 1 * PLANE_B, tid);
            ld_plane(Bhi, rowB, K, k0, st + 2 * PLANE_B, tid);
            ld_plane(Blo, rowB, K, k0, st + 3 * PLANE_B, tid);
            CP_COMMIT();
            CP_WAIT(1);
        } else {
            CP_WAIT(0);
        }
        __syncthreads();

        char* st = smem + cur * STAGE_B;
        const uint32_t aB  = smem_to_u32(st) + (wm * 64) * ASTR_B;
        const uint32_t bB  = smem_to_u32(st) + 2 * PLANE_B + (wn * 32) * ASTR_B;

#pragma unroll
        for (int s = 0; s < 2; s++) {
            const int koff = s * 32;        // bytes (16 halves)
            uint32_t ahi[4][4], alo[4][4];
#pragma unroll
            for (int mt = 0; mt < 4; mt++) {
                uint32_t addr = aB + (mt * 16 + a_r) * ASTR_B + a_c + koff;
                LDSM_X4(ahi[mt], addr);
                LDSM_X4(alo[mt], addr + PLANE_B);
            }
#pragma unroll
            for (int np = 0; np < 2; np++) {
                uint32_t baddr = bB + (np * 16 + b_r) * ASTR_B + b_c + koff;
                uint32_t bh[4], bl[4];
                LDSM_X4(bh, baddr);
                LDSM_X4(bl, baddr + PLANE_B);
#pragma unroll
                for (int mt = 0; mt < 4; mt++) {
                    mma16816(acc[mt][np * 2 + 0], ahi[mt], bh + 0);
                    mma16816(acc[mt][np * 2 + 0], alo[mt], bh + 0);
                    mma16816(acc[mt][np * 2 + 0], ahi[mt], bl + 0);
                    mma16816(acc[mt][np * 2 + 1], ahi[mt], bh + 2);
                    mma16816(acc[mt][np * 2 + 1], alo[mt], bh + 2);
                    mma16816(acc[mt][np * 2 + 1], ahi[mt], bl + 2);
                }
            }
        }
        __syncthreads();
    }

    // epilogue
#pragma unroll
    for (int mt = 0; mt < 4; mt++) {
#pragma unroll
        for (int half = 0; half < 2; half++) {
            int gr = by * 128 + wm * 64 + mt * 16 + g + half * 8;
            if (revC) gr = (gr & ~(L_SEQ - 1)) | ((L_SEQ - 1) - (gr & (L_SEQ - 1)));
            float* crow = C + (size_t)gr * Nc;
#pragma unroll
            for (int nt = 0; nt < 4; nt++) {
                int gc = bx * 128 + wn * 32 + nt * 8 + tg * 2;
                if (gc + 1 < Nc) {
                    float v0 = acc[mt][nt][half * 2 + 0];
                    float v1 = acc[mt][nt][half * 2 + 1];
                    if (accC) { v0 += crow[gc]; v1 += crow[gc + 1]; }
                    crow[gc]     = v0;
                    crow[gc + 1] = v1;
                }
            }
        }
    }
}

// ---------------------------------------------------------------------------
// fp16 split helpers / kernels
// ---------------------------------------------------------------------------
__device__ __forceinline__ void hsplit(float v, __half& h, __half& l)
{
    h = __float2half(v);
    l = __float2half(v - __half2float(h));
}

__global__ __launch_bounds__(256) void split_rows_kernel(
    const float* __restrict__ in, __half* __restrict__ hi, __half* __restrict__ lo, size_t n4)
{
    size_t i = (size_t)blockIdx.x * blockDim.x + threadIdx.x;
    if (i >= n4) return;
    float4 v = ((const float4*)in)[i];
    __half h0, l0, h1, l1, h2, l2, h3, l3;
    hsplit(v.x, h0, l0); hsplit(v.y, h1, l1); hsplit(v.z, h2, l2); hsplit(v.w, h3, l3);
    ((__half2*)hi)[i * 2 + 0] = __halves2half2(h0, h1);
    ((__half2*)hi)[i * 2 + 1] = __halves2half2(h2, h3);
    ((__half2*)lo)[i * 2 + 0] = __halves2half2(l0, l1);
    ((__half2*)lo)[i * 2 + 1] = __halves2half2(l2, l3);
}

// W[K, Nv] -> W^T hi/lo [Npad, K] (zero-pad rows n >= Nv)
__global__ void split_transpose_kernel(
    const float* __restrict__ W, __half* __restrict__ bh, __half* __restrict__ bl,
    int K, int Nv)
{
    __shared__ float t[32][33];
    const int n0 = blockIdx.x * 32, k0 = blockIdx.y * 32;
    const int tx = threadIdx.x, ty = threadIdx.y;
#pragma unroll
    for (int i = 0; i < 32; i += 8) {
        int n = n0 + tx;
        t[ty + i][tx] = (n < Nv) ? W[(size_t)(k0 + ty + i) * Nv + n] : 0.f;
    }
    __syncthreads();
#pragma unroll
    for (int i = 0; i < 32; i += 8) {
        int n = n0 + ty + i, k = k0 + tx;
        float v = t[tx][ty + i];
        __half h, l;
        hsplit(v, h, l);
        bh[(size_t)n * K + k] = h;
        bl[(size_t)n * K + k] = l;
    }
}

// ---------------------------------------------------------------------------
// Depthwise causal conv1d (D_CONV=4) + SiLU; emits fp32 xi + fp16 hi/lo planes
// ---------------------------------------------------------------------------
__global__ __launch_bounds__(256) void conv_silu_kernel(
    const float* __restrict__ conv_w, const float* __restrict__ conv_b)
{
    size_t idx = (size_t)blockIdx.x * blockDim.x + threadIdx.x;
    if (idx >= (size_t)M_ROWS * E_DIM) return;
    int e = (int)(idx & (E_DIM - 1));
    int m = (int)(idx >> 11);
    int l = m & (L_SEQ - 1);

    float acc = conv_b[e];
#pragma unroll
    for (int kk = 0; kk < 4; kk++) {
        int ll = l - 3 + kk;
        if (ll >= 0)
            acc = fmaf(g_xz[(size_t)(m - 3 + kk) * TWO_E + e], conv_w[e * 4 + kk], acc);
    }
    float v = acc / (1.f + __expf(-acc));
    g_xi[idx] = v;
    __half h, lo;
    hsplit(v, h, lo);
    g_xihi[idx] = h;
    g_xilo[idx] = lo;
}

// ---------------------------------------------------------------------------
// delta = softplus( proj[:, :64] @ dt_w + dt_b )
// ---------------------------------------------------------------------------
__device__ __forceinline__ float softplusf(float x)
{
    return (x > 20.f) ? x : log1pf(__expf(x));
}

__global__ __launch_bounds__(256) void delta_kernel(
    const float* __restrict__ dt_w, const float* __restrict__ dt_b)
{
    __shared__ float s[DT_RANK];
    const int m = blockIdx.y;
    const int e = (blockIdx.x * 256 + threadIdx.x) * 4;
    if (threadIdx.x < DT_RANK) s[threadIdx.x] = g_proj[(size_t)m * PROJ_N + threadIdx.x];
    __syncthreads();

    float4 acc = *(const float4*)(dt_b + e);
#pragma unroll 8
    for (int r = 0; r < DT_RANK; r++) {
        float4 w = *(const float4*)(dt_w + (size_t)r * E_DIM + e);
        float sv = s[r];
        acc.x = fmaf(sv, w.x, acc.x);
        acc.y = fmaf(sv, w.y, acc.y);
        acc.z = fmaf(sv, w.z, acc.z);
        acc.w = fmaf(sv, w.w, acc.w);
    }
    float4 o;
    o.x = softplusf(acc.x);
    o.y = softplusf(acc.y);
    o.z = softplusf(acc.z);
    o.w = softplusf(acc.w);
    *(float4*)(g_delta + (size_t)m * E_DIM + e) = o;
}

// ---------------------------------------------------------------------------
// Selective scan: 16 lanes per chain (lane = state n), 2 chains/warp.
// ---------------------------------------------------------------------------
__global__ __launch_bounds__(256) void scan_kernel(const float* __restrict__ A_log)
{
    const int lane = threadIdx.x & 31;
    const int w = blockIdx.x * (blockDim.x >> 5) + (threadIdx.x >> 5);
    const int half = lane >> 4;
    const int n = lane & 15;
    const int chain = 2 * w + half;
    const int b = chain >> 11;
    const int e = chain & (E_DIM - 1);

    const float a = -__expf(A_log[e * N_ST + n]);
    const float a0 = __shfl_sync(0xffffffffu, a, lane & 16);
    const float kf = rintf(a / a0);
    const int k = (int)kf;
    const bool ok = (fabsf(a - kf * a0) <= 1e-5f * fmaxf(fabsf(a), 1e-20f)) &&
                    (k >= 1) && (k <= 16);
    const bool fast = __all_sync(0xffffffffu, ok);

    const float* dp = g_delta + (size_t)b * L_SEQ * E_DIM + e;
    const float* up = g_xi    + (size_t)b * L_SEQ * E_DIM + e;
    const float* pp = g_proj  + (size_t)b * L_SEQ * PROJ_N;
    float*       yp = g_y     + (size_t)b * L_SEQ * E_DIM + e;

    float h = 0.f;
    float d  = dp[0];
    float u  = up[0];
    float Bv = pp[64 + n];
    float Cv = pp[80 + n];

    for (int l = 0; l < L_SEQ; l++) {
        float dn = 0.f, un = 0.f, Bn = 0.f, Cn = 0.f;
        if (l + 1 < L_SEQ) {
            dn = dp[(size_t)(l + 1) * E_DIM];
            un = up[(size_t)(l + 1) * E_DIM];
            Bn = pp[(l + 1) * PROJ_N + 64 + n];
            Cn = pp[(l + 1) * PROJ_N + 80 + n];
        }

        float decay;
        if (fast) {
            float p = __expf(d * a0);
            float p2 = p * p, p4 = p2 * p2, p8 = p4 * p4;
            decay = 1.f;
            if (k & 1)  decay *= p;
            if (k & 2)  decay *= p2;
            if (k & 4)  decay *= p4;
            if (k & 8)  decay *= p8;
            if (k & 16) decay *= p8 * p8;
        } else {
            decay = __expf(d * a);
        }

        h = fmaf(decay, h, d * u * Bv);

        float v = h * Cv;
        v += __shfl_xor_sync(0xffffffffu, v, 1);
        v += __shfl_xor_sync(0xffffffffu, v, 2);
        v += __shfl_xor_sync(0xffffffffu, v, 4);
        v += __shfl_xor_sync(0xffffffffu, v, 8);
        if (n == 0) yp[(size_t)l * E_DIM] = v;

        d = dn; u = un; Bv = Bn; Cv = Cn;
    }
}

// ---------------------------------------------------------------------------
// y = (y_scan + xi*Dp) * silu(z) -> fp16 hi/lo planes for the out-proj GEMM
// ---------------------------------------------------------------------------
__global__ __launch_bounds__(256) void combine_kernel(const float* __restrict__ Dp)
{
    size_t idx = (size_t)blockIdx.x * blockDim.x + threadIdx.x;
    if (idx >= (size_t)M_ROWS * E_DIM) return;
    int e = (int)(idx & (E_DIM - 1));
    size_t m = idx >> 11;
    float z = g_xz[m * TWO_E + E_DIM + e];
    float sz = z / (1.f + __expf(-z));
    float v = (g_y[idx] + g_xi[idx] * Dp[e]) * sz;
    __half h, lo;
    hsplit(v, h, lo);
    g_yhi[idx] = h;
    g_ylo[idx] = lo;
}

// ---------------------------------------------------------------------------
// Launcher
// ---------------------------------------------------------------------------
extern "C" void kernel_launch(void* const* d_in, const int* in_sizes, int n_in,
                              void* d_out, int out_size)
{
    (void)in_sizes; (void)n_in; (void)out_size;
    const float* x = (const float*)d_in[0];
    float* out = (float*)d_out;

    cudaFuncSetAttribute(hmma_gemm, cudaFuncAttributeMaxDynamicSharedMemorySize, GEMM_SMEM);

    __half *xhi, *xlo, *xihi, *xilo, *yhi, *ylo;
    __half *btin_h, *btin_l, *btxp_h, *btxp_l, *btout_h, *btout_l;
    float *p_xz, *p_proj;
    cudaGetSymbolAddress((void**)&xhi, g_xhi);
    cudaGetSymbolAddress((void**)&xlo, g_xlo);
    cudaGetSymbolAddress((void**)&xihi, g_xihi);
    cudaGetSymbolAddress((void**)&xilo, g_xilo);
    cudaGetSymbolAddress((void**)&yhi, g_yhi);
    cudaGetSymbolAddress((void**)&ylo, g_ylo);
    cudaGetSymbolAddress((void**)&btin_h, g_btin_hi);
    cudaGetSymbolAddress((void**)&btin_l, g_btin_lo);
    cudaGetSymbolAddress((void**)&btxp_h, g_btxp_hi);
    cudaGetSymbolAddress((void**)&btxp_l, g_btxp_lo);
    cudaGetSymbolAddress((void**)&btout_h, g_btout_hi);
    cudaGetSymbolAddress((void**)&btout_l, g_btout_lo);
    cudaGetSymbolAddress((void**)&p_xz, g_xz);
    cudaGetSymbolAddress((void**)&p_proj, g_proj);

    const size_t elems_e = (size_t)M_ROWS * E_DIM;
    const int blocks_e = (int)((elems_e + 255) / 256);

    // split x once (row reversal handled in GEMM epilogues)
    {
        size_t n4 = (size_t)M_ROWS * D_MODEL / 4;
        split_rows_kernel<<<(unsigned)((n4 + 255) / 256), 256>>>(x, xhi, xlo, n4);
    }

    for (int dir = 0; dir < 2; dir++) {
        const float* in_w    = (const float*)d_in[1 + dir * 9 + 0];
        const float* conv_w  = (const float*)d_in[1 + dir * 9 + 1];
        const float* conv_b  = (const float*)d_in[1 + dir * 9 + 2];
        const float* xproj_w = (const float*)d_in[1 + dir * 9 + 3];
        const float* dt_w    = (const float*)d_in[1 + dir * 9 + 4];
        const float* dt_b    = (const float*)d_in[1 + dir * 9 + 5];
        const float* A_log   = (const float*)d_in[1 + dir * 9 + 6];
        const float* Dp      = (const float*)d_in[1 + dir * 9 + 7];
        const float* out_w   = (const float*)d_in[1 + dir * 9 + 8];

        // 1) xz[rev_dir] = x @ in_w
        split_transpose_kernel<<<dim3(TWO_E / 32, D_MODEL / 32), dim3(32, 8)>>>(
            in_w, btin_h, btin_l, D_MODEL, TWO_E);
        hmma_gemm<<<dim3(TWO_E / 128, M_ROWS / 128), 256, GEMM_SMEM>>>(
            xhi, xlo, btin_h, btin_l, p_xz, D_MODEL, TWO_E, dir, 0);

        // 2) xi = silu(causal_conv(xz[:, :E]))  (+ fp16 planes)
        conv_silu_kernel<<<blocks_e, 256>>>(conv_w, conv_b);

        // 3) proj = xi @ xproj_w   (N=96, padded to 128)
        split_transpose_kernel<<<dim3(128 / 32, E_DIM / 32), dim3(32, 8)>>>(
            xproj_w, btxp_h, btxp_l, E_DIM, PROJ_N);
        hmma_gemm<<<dim3(1, M_ROWS / 128), 256, GEMM_SMEM>>>(
            xihi, xilo, btxp_h, btxp_l, p_proj, E_DIM, PROJ_N, 0, 0);

        // 4) delta = softplus(proj[:, :64] @ dt_w + dt_b)
        delta_kernel<<<dim3(E_DIM / 1024, M_ROWS), 256>>>(dt_w, dt_b);

        // 5) selective scan -> g_y
        scan_kernel<<<512, 256>>>(A_log);

        // 6) y = (y + xi*Dp) * silu(z)  -> fp16 planes
        combine_kernel<<<blocks_e, 256>>>(Dp);

        // 7) out (+)= y @ out_w  (rows reversed + accumulate for bwd)
        split_transpose_kernel<<<dim3(D_MODEL / 32, E_DIM / 32), dim3(32, 8)>>>(
            out_w, btout_h, btout_l, E_DIM, D_MODEL);
        hmma_gemm<<<dim3(D_MODEL / 128, M_ROWS / 128), 256, GEMM_SMEM>>>(
            yhi, ylo, btout_h, btout_l, out, E_DIM, D_MODEL, dir, dir);
    }
}

// round 6
// speedup vs baseline: 2.2901x; 1.3661x over previous
#include <cuda_runtime.h>
#include <cuda_fp16.h>
#include <math.h>
#include <stdint.h>

// ---------------------------------------------------------------------------
// BidirectionalMamba: D=1024, E=2048, N=16, dt_rank=64, B=4, L=2048.
// Both directions processed in ORIGINAL time order:
//   fwd: causal conv, forward scan.
//   bwd: anti-causal conv (flipped taps), backward scan.  This makes the
//   in-proj and out-proj each a single big GEMM with no row reversal.
// ---------------------------------------------------------------------------
#define D_MODEL  1024
#define E_DIM    2048
#define FOUR_E   4096          // 2 dirs * E
#define EIGHT_E  8192          // 2 dirs * 2E (in-proj output width)
#define N_ST     16
#define DT_RANK  64
#define PROJ_N   96
#define B_SZ     4
#define L_SEQ    2048
#define M_ROWS   8192

// ---------------------------------------------------------------------------
// Scratch (device globals)
// ---------------------------------------------------------------------------
__device__ float g_xz[(size_t)M_ROWS * EIGHT_E];      // [M, 8192]: xiF|zF|xiB|zB
__device__ float g_xi[(size_t)M_ROWS * FOUR_E];       // [M, 4096]: xiF|xiB (post conv+silu)
__device__ float g_delta[(size_t)M_ROWS * FOUR_E];    // [M, 4096]
__device__ float g_proj[(size_t)2 * M_ROWS * PROJ_N]; // per-dir [M, 96]
__device__ float g_y[(size_t)M_ROWS * FOUR_E];        // [M, 4096]

// fp16 split planes (A operands)
__device__ __half g_xhi[(size_t)M_ROWS * D_MODEL];
__device__ __half g_xlo[(size_t)M_ROWS * D_MODEL];
__device__ __half g_xihi[(size_t)M_ROWS * FOUR_E];
__device__ __half g_xilo[(size_t)M_ROWS * FOUR_E];
__device__ __half g_yhi[(size_t)M_ROWS * FOUR_E];
__device__ __half g_ylo[(size_t)M_ROWS * FOUR_E];
// transposed weight hi-planes W^T [Npad, K]
__device__ __half g_btin[(size_t)EIGHT_E * D_MODEL];   // [8192, 1024]
__device__ __half g_btxp[(size_t)2 * 128 * E_DIM];     // per dir [128, 2048]
__device__ __half g_btout[(size_t)D_MODEL * FOUR_E];   // [1024, 4096]

// ---------------------------------------------------------------------------
// helpers
// ---------------------------------------------------------------------------
__device__ __forceinline__ uint32_t smem_to_u32(const void* p)
{
    uint32_t a;
    asm("{ .reg .u64 t; cvta.to.shared.u64 t, %1; cvt.u32.u64 %0, t; }" : "=r"(a) : "l"(p));
    return a;
}

#define LDSM_X4(r, a) \
    asm volatile("ldmatrix.sync.aligned.m8n8.x4.shared.b16 {%0,%1,%2,%3}, [%4];" \
        : "=r"((r)[0]), "=r"((r)[1]), "=r"((r)[2]), "=r"((r)[3]) : "r"(a))

__device__ __forceinline__ void mma16816(float* d, const uint32_t* a, const uint32_t* b)
{
    asm volatile(
        "mma.sync.aligned.m16n8k16.row.col.f32.f16.f16.f32 "
        "{%0,%1,%2,%3}, {%4,%5,%6,%7}, {%8,%9}, {%0,%1,%2,%3};"
        : "+f"(d[0]), "+f"(d[1]), "+f"(d[2]), "+f"(d[3])
        : "r"(a[0]), "r"(a[1]), "r"(a[2]), "r"(a[3]), "r"(b[0]), "r"(b[1]));
}

#define CP_ASYNC16(dst, src) \
    asm volatile("cp.async.cg.shared.global [%0], [%1], 16;" :: "r"(dst), "l"(src))
#define CP_COMMIT()  asm volatile("cp.async.commit_group;" ::: "memory")
#define CP_WAIT(n)   asm volatile("cp.async.wait_group %0;" :: "n"(n) : "memory")

// ---------------------------------------------------------------------------
// 2-term split-fp16 HMMA GEMM: C[M,N] = A[M,K] @ W[K,N]  (B = W^T hi-plane).
// A = Ahi + Alo (fp16 planes); products: Ahi*B + Alo*B.
// Block tile 128x128, BK=32, 256 threads (8 warps 2x4), warp tile 64x32.
// lda: row stride of A planes in elements (supports column-slice views).
// ---------------------------------------------------------------------------
#define ASTR_B      80                      // padded row pitch bytes (32 halves + pad)
#define PLANE_B     (128 * ASTR_B)          // 10240
#define STAGE_B     (3 * PLANE_B)           // 30720 (Ahi, Alo, Bhi)
#define GEMM_SMEM   (2 * STAGE_B)           // 61440

__device__ __forceinline__ void ld_plane(
    const __half* __restrict__ gsrc, int row0, int lda, int k0, char* stp, int tid)
{
#pragma unroll
    for (int j = 0; j < 2; j++) {
        int cid = j * 256 + tid;            // 0..511
        int r = cid >> 2;
        int c = cid & 3;
        const void* src = gsrc + (size_t)(row0 + r) * lda + k0 + c * 8;
        uint32_t dst = smem_to_u32(stp + r * ASTR_B + c * 16);
        CP_ASYNC16(dst, src);
    }
}

__global__ __launch_bounds__(256) void hmma_gemm(
    const __half* __restrict__ Ahi, const __half* __restrict__ Alo,
    const __half* __restrict__ Bhi,
    float* __restrict__ C, int lda, int K, int Nc)
{
    extern __shared__ char smem[];
    const int tid  = threadIdx.x;
    const int lane = tid & 31;
    const int warp = tid >> 5;
    const int wm   = warp & 1;
    const int wn   = warp >> 1;
    const int g    = lane >> 2;
    const int tg   = lane & 3;
    const int bx = blockIdx.x;
    const int by = blockIdx.y;
    const int rowA = by * 128;
    const int rowB = bx * 128;

    float acc[4][4][4];
#pragma unroll
    for (int i = 0; i < 4; i++)
#pragma unroll
        for (int j = 0; j < 4; j++)
#pragma unroll
            for (int r = 0; r < 4; r++) acc[i][j][r] = 0.f;

    const int a_r = lane & 15;
    const int a_c = (lane >> 4) * 16;
    const int b_r = (lane & 7) + (((lane >> 4) & 1) << 3);
    const int b_c = ((lane >> 3) & 1) * 16;

    const int T = K >> 5;

    {
        char* st = smem;
        ld_plane(Ahi, rowA, lda, 0, st + 0 * PLANE_B, tid);
        ld_plane(Alo, rowA, lda, 0, st + 1 * PLANE_B, tid);
        ld_plane(Bhi, rowB, K,   0, st + 2 * PLANE_B, tid);
        CP_COMMIT();
    }

    for (int t = 0; t < T; t++) {
        const int cur = t & 1;
        if (t + 1 < T) {
            char* st = smem + (cur ^ 1) * STAGE_B;
            const int k0 = (t + 1) << 5;
            ld_plane(Ahi, rowA, lda, k0, st + 0 * PLANE_B, tid);
            ld_plane(Alo, rowA, lda, k0, st + 1 * PLANE_B, tid);
            ld_plane(Bhi, rowB, K,   k0, st + 2 * PLANE_B, tid);
            CP_COMMIT();
            CP_WAIT(1);
        } else {
            CP_WAIT(0);
        }
        __syncthreads();

        char* st = smem + cur * STAGE_B;
        const uint32_t aB = smem_to_u32(st) + (wm * 64) * ASTR_B;
        const uint32_t bB = smem_to_u32(st) + 2 * PLANE_B + (wn * 32) * ASTR_B;

#pragma unroll
        for (int s = 0; s < 2; s++) {
            const int koff = s * 32;
            uint32_t ahi[4][4], alo[4][4];
#pragma unroll
            for (int mt = 0; mt < 4; mt++) {
                uint32_t addr = aB + (mt * 16 + a_r) * ASTR_B + a_c + koff;
                LDSM_X4(ahi[mt], addr);
                LDSM_X4(alo[mt], addr + PLANE_B);
            }
#pragma unroll
            for (int np = 0; np < 2; np++) {
                uint32_t baddr = bB + (np * 16 + b_r) * ASTR_B + b_c + koff;
                uint32_t bh[4];
                LDSM_X4(bh, baddr);
#pragma unroll
                for (int mt = 0; mt < 4; mt++) {
                    mma16816(acc[mt][np * 2 + 0], ahi[mt], bh + 0);
                    mma16816(acc[mt][np * 2 + 0], alo[mt], bh + 0);
                    mma16816(acc[mt][np * 2 + 1], ahi[mt], bh + 2);
                    mma16816(acc[mt][np * 2 + 1], alo[mt], bh + 2);
                }
            }
        }
        __syncthreads();
    }

#pragma unroll
    for (int mt = 0; mt < 4; mt++) {
#pragma unroll
        for (int half = 0; half < 2; half++) {
            int gr = by * 128 + wm * 64 + mt * 16 + g + half * 8;
            float* crow = C + (size_t)gr * Nc;
#pragma unroll
            for (int nt = 0; nt < 4; nt++) {
                int gc = bx * 128 + wn * 32 + nt * 8 + tg * 2;
                if (gc + 1 < Nc) {
                    crow[gc]     = acc[mt][nt][half * 2 + 0];
                    crow[gc + 1] = acc[mt][nt][half * 2 + 1];
                }
            }
        }
    }
}

// ---------------------------------------------------------------------------
// fp16 split helpers / prep kernels
// ---------------------------------------------------------------------------
__device__ __forceinline__ void hsplit(float v, __half& h, __half& l)
{
    h = __float2half(v);
    l = __float2half(v - __half2float(h));
}

__global__ __launch_bounds__(256) void split_rows_kernel(
    const float* __restrict__ in, __half* __restrict__ hi, __half* __restrict__ lo, size_t n4)
{
    size_t i = (size_t)blockIdx.x * blockDim.x + threadIdx.x;
    if (i >= n4) return;
    float4 v = ((const float4*)in)[i];
    __half h0, l0, h1, l1, h2, l2, h3, l3;
    hsplit(v.x, h0, l0); hsplit(v.y, h1, l1); hsplit(v.z, h2, l2); hsplit(v.w, h3, l3);
    ((__half2*)hi)[i * 2 + 0] = __halves2half2(h0, h1);
    ((__half2*)hi)[i * 2 + 1] = __halves2half2(h2, h3);
    ((__half2*)lo)[i * 2 + 0] = __halves2half2(l0, l1);
    ((__half2*)lo)[i * 2 + 1] = __halves2half2(l2, l3);
}

// W[Ksrc, Nv] -> bh[n*Ktot + koff + k] (hi plane only, zero-pad n beyond Nv)
__global__ void transpose_h_kernel(
    const float* __restrict__ W, __half* __restrict__ bh, int Ktot, int koff, int Nv)
{
    __shared__ float t[32][33];
    const int n0 = blockIdx.x * 32, k0 = blockIdx.y * 32;
    const int tx = threadIdx.x, ty = threadIdx.y;
#pragma unroll
    for (int i = 0; i < 32; i += 8) {
        int n = n0 + tx;
        t[ty + i][tx] = (n < Nv) ? W[(size_t)(k0 + ty + i) * Nv + n] : 0.f;
    }
    __syncthreads();
#pragma unroll
    for (int i = 0; i < 32; i += 8) {
        int n = n0 + ty + i, k = k0 + tx;
        bh[(size_t)n * Ktot + koff + k] = __float2half(t[tx][ty + i]);
    }
}

// ---------------------------------------------------------------------------
// Depthwise conv1d (D_CONV=4) + SiLU, both directions in one pass.
// dir 0 (cols 0:2048): causal,      taps m-3..m,  weights w[0..3]
// dir 1 (cols 2048:4096): anti-causal, taps m..m+3, weights w[3..0]
// ---------------------------------------------------------------------------
__global__ __launch_bounds__(256) void conv_silu_kernel(
    const float* __restrict__ cwf, const float* __restrict__ cbf,
    const float* __restrict__ cwb, const float* __restrict__ cbb)
{
    size_t idx = (size_t)blockIdx.x * blockDim.x + threadIdx.x;
    if (idx >= (size_t)M_ROWS * FOUR_E) return;
    const int c = (int)(idx & (FOUR_E - 1));
    const int m = (int)(idx >> 12);
    const int dir = c >> 11;
    const int e = c & (E_DIM - 1);
    const int l = m & (L_SEQ - 1);

    const float* cw = dir ? cwb : cwf;
    const float* cb = dir ? cbb : cbf;
    const float* src = g_xz + (size_t)m * EIGHT_E + dir * 4096 + e;

    float acc = cb[e];
#pragma unroll
    for (int t = 0; t < 4; t++) {
        int off  = dir ? t : t - 3;
        int widx = dir ? 3 - t : t;
        int ll = l + off;
        if (ll >= 0 && ll < L_SEQ)
            acc = fmaf(src[(ptrdiff_t)off * EIGHT_E], cw[e * 4 + widx], acc);
    }
    float v = acc / (1.f + __expf(-acc));
    g_xi[idx] = v;
    __half h, lo;
    hsplit(v, h, lo);
    g_xihi[idx] = h;
    g_xilo[idx] = lo;
}

// ---------------------------------------------------------------------------
// delta = softplus( proj[:, :64] @ dt_w + dt_b );  8 m-rows per block so each
// dt_w float4 feeds 32 FMAs.  grid: (E/1024, M/8, 2 dirs), block 256.
// ---------------------------------------------------------------------------
__device__ __forceinline__ float softplusf(float x)
{
    return (x > 20.f) ? x : log1pf(__expf(x));
}

__global__ __launch_bounds__(256) void delta_kernel(
    const float* __restrict__ dtw_f, const float* __restrict__ dtb_f,
    const float* __restrict__ dtw_b, const float* __restrict__ dtb_b)
{
    __shared__ float s[8][DT_RANK];
    const int dir = blockIdx.z;
    const float* dtw = dir ? dtw_b : dtw_f;
    const float* dtb = dir ? dtb_b : dtb_f;
    const int m0 = blockIdx.y * 8;
    const int col = blockIdx.x * 1024 + threadIdx.x * 4;

    const float* pbase = g_proj + (size_t)dir * M_ROWS * PROJ_N;
#pragma unroll
    for (int i = threadIdx.x; i < 8 * DT_RANK; i += 256) {
        int row = i >> 6, r = i & 63;
        s[row][r] = pbase[(size_t)(m0 + row) * PROJ_N + r];
    }
    __syncthreads();

    float4 bias = *(const float4*)(dtb + col);
    float4 acc[8];
#pragma unroll
    for (int row = 0; row < 8; row++) acc[row] = bias;

#pragma unroll 4
    for (int r = 0; r < DT_RANK; r++) {
        float4 w = *(const float4*)(dtw + (size_t)r * E_DIM + col);
#pragma unroll
        for (int row = 0; row < 8; row++) {
            float sv = s[row][r];
            acc[row].x = fmaf(sv, w.x, acc[row].x);
            acc[row].y = fmaf(sv, w.y, acc[row].y);
            acc[row].z = fmaf(sv, w.z, acc[row].z);
            acc[row].w = fmaf(sv, w.w, acc[row].w);
        }
    }
#pragma unroll
    for (int row = 0; row < 8; row++) {
        float4 o;
        o.x = softplusf(acc[row].x);
        o.y = softplusf(acc[row].y);
        o.z = softplusf(acc[row].z);
        o.w = softplusf(acc[row].w);
        *(float4*)(g_delta + (size_t)(m0 + row) * FOUR_E + dir * E_DIM + col) = o;
    }
}

// ---------------------------------------------------------------------------
// Selective scan, both directions: 16 lanes/chain (lane = state n), 2
// chains/warp.  dir 1 iterates time backwards.  16384 chains total.
// ---------------------------------------------------------------------------
__global__ __launch_bounds__(256) void scan_kernel(
    const float* __restrict__ Alog_f, const float* __restrict__ Alog_b)
{
    const int lane = threadIdx.x & 31;
    const int w = blockIdx.x * (blockDim.x >> 5) + (threadIdx.x >> 5);
    const int half = lane >> 4;
    const int n = lane & 15;
    const int chain = 2 * w + half;             // 0..16383
    const int dir = chain >> 13;
    const int b = (chain >> 11) & 3;
    const int e = chain & (E_DIM - 1);
    const int col = dir * E_DIM + e;

    const float* Al = dir ? Alog_b : Alog_f;
    const float a = -__expf(Al[e * N_ST + n]);
    const float a0 = __shfl_sync(0xffffffffu, a, lane & 16);
    const float kf = rintf(a / a0);
    const int k = (int)kf;
    const bool ok = (fabsf(a - kf * a0) <= 1e-5f * fmaxf(fabsf(a), 1e-20f)) &&
                    (k >= 1) && (k <= 16);
    const bool fast = __all_sync(0xffffffffu, ok);

    const int l0 = dir ? (L_SEQ - 1) : 0;
    const ptrdiff_t strideE = dir ? -FOUR_E : FOUR_E;
    const ptrdiff_t strideP = dir ? -PROJ_N : PROJ_N;

    const float* dp = g_delta + (size_t)(b * L_SEQ + l0) * FOUR_E + col;
    const float* up = g_xi    + (size_t)(b * L_SEQ + l0) * FOUR_E + col;
    const float* pp = g_proj  + (size_t)dir * M_ROWS * PROJ_N
                             + (size_t)(b * L_SEQ + l0) * PROJ_N;
    float*       yp = g_y     + (size_t)(b * L_SEQ + l0) * FOUR_E + col;

    float h = 0.f;
    float d  = dp[0];
    float u  = up[0];
    float Bv = pp[64 + n];
    float Cv = pp[80 + n];

    for (int i = 0; i < L_SEQ; i++) {
        float dn = 0.f, un = 0.f, Bn = 0.f, Cn = 0.f;
        if (i + 1 < L_SEQ) {
            dn = dp[strideE];
            un = up[strideE];
            Bn = pp[strideP + 64 + n];
            Cn = pp[strideP + 80 + n];
        }

        float decay;
        if (fast) {
            float p = __expf(d * a0);
            float p2 = p * p, p4 = p2 * p2, p8 = p4 * p4;
            decay = 1.f;
            if (k & 1)  decay *= p;
            if (k & 2)  decay *= p2;
            if (k & 4)  decay *= p4;
            if (k & 8)  decay *= p8;
            if (k & 16) decay *= p8 * p8;
        } else {
            decay = __expf(d * a);
        }

        h = fmaf(decay, h, d * u * Bv);

        float v = h * Cv;
        v += __shfl_xor_sync(0xffffffffu, v, 1);
        v += __shfl_xor_sync(0xffffffffu, v, 2);
        v += __shfl_xor_sync(0xffffffffu, v, 4);
        v += __shfl_xor_sync(0xffffffffu, v, 8);
        if (n == 0) *yp = v;

        dp += strideE; up += strideE; yp += strideE; pp += strideP;
        d = dn; u = un; Bv = Bn; Cv = Cn;
    }
}

// ---------------------------------------------------------------------------
// y = (y_scan + xi*Dp) * silu(z) -> fp16 hi/lo planes (both dirs)
// ---------------------------------------------------------------------------
__global__ __launch_bounds__(256) void combine_kernel(
    const float* __restrict__ Dp_f, const float* __restrict__ Dp_b)
{
    size_t idx = (size_t)blockIdx.x * blockDim.x + threadIdx.x;
    if (idx >= (size_t)M_ROWS * FOUR_E) return;
    const int c = (int)(idx & (FOUR_E - 1));
    const size_t m = idx >> 12;
    const int dir = c >> 11;
    const int e = c & (E_DIM - 1);
    const float* Dp = dir ? Dp_b : Dp_f;

    float z = g_xz[m * EIGHT_E + dir * 4096 + 2048 + e];
    float sz = z / (1.f + __expf(-z));
    float v = (g_y[idx] + g_xi[idx] * Dp[e]) * sz;
    __half h, lo;
    hsplit(v, h, lo);
    g_yhi[idx] = h;
    g_ylo[idx] = lo;
}

// ---------------------------------------------------------------------------
// Launcher
// ---------------------------------------------------------------------------
extern "C" void kernel_launch(void* const* d_in, const int* in_sizes, int n_in,
                              void* d_out, int out_size)
{
    (void)in_sizes; (void)n_in; (void)out_size;
    const float* x = (const float*)d_in[0];
    float* out = (float*)d_out;

    cudaFuncSetAttribute(hmma_gemm, cudaFuncAttributeMaxDynamicSharedMemorySize, GEMM_SMEM);

    const float* P[2][9];
    for (int dir = 0; dir < 2; dir++)
        for (int j = 0; j < 9; j++)
            P[dir][j] = (const float*)d_in[1 + dir * 9 + j];
    // indices: 0 in_w, 1 conv_w, 2 conv_b, 3 xproj_w, 4 dt_w, 5 dt_b, 6 A_log, 7 Dp, 8 out_w

    __half *xhi, *xlo, *xihi, *xilo, *yhi, *ylo, *btin, *btxp, *btout;
    float *p_xz, *p_proj;
    cudaGetSymbolAddress((void**)&xhi, g_xhi);
    cudaGetSymbolAddress((void**)&xlo, g_xlo);
    cudaGetSymbolAddress((void**)&xihi, g_xihi);
    cudaGetSymbolAddress((void**)&xilo, g_xilo);
    cudaGetSymbolAddress((void**)&yhi, g_yhi);
    cudaGetSymbolAddress((void**)&ylo, g_ylo);
    cudaGetSymbolAddress((void**)&btin, g_btin);
    cudaGetSymbolAddress((void**)&btxp, g_btxp);
    cudaGetSymbolAddress((void**)&btout, g_btout);
    cudaGetSymbolAddress((void**)&p_xz, g_xz);
    cudaGetSymbolAddress((void**)&p_proj, g_proj);

    // ---- weight prep (hi planes, transposed) ----
    // in-proj: [8192, 1024]  (rows 0:4096 fwd, 4096:8192 bwd)
    transpose_h_kernel<<<dim3(128, 32), dim3(32, 8)>>>(P[0][0], btin, D_MODEL, 0, 4096);
    transpose_h_kernel<<<dim3(128, 32), dim3(32, 8)>>>(
        P[1][0], btin + (size_t)4096 * D_MODEL, D_MODEL, 0, 4096);
    // xproj per dir: [128, 2048]
    for (int dir = 0; dir < 2; dir++)
        transpose_h_kernel<<<dim3(4, 64), dim3(32, 8)>>>(
            P[dir][3], btxp + (size_t)dir * 128 * E_DIM, E_DIM, 0, PROJ_N);
    // out-proj: [1024, 4096]  (k 0:2048 fwd, 2048:4096 bwd)
    transpose_h_kernel<<<dim3(32, 64), dim3(32, 8)>>>(P[0][8], btout, FOUR_E, 0, D_MODEL);
    transpose_h_kernel<<<dim3(32, 64), dim3(32, 8)>>>(P[1][8], btout, FOUR_E, 2048, D_MODEL);

    // ---- split x ----
    {
        size_t n4 = (size_t)M_ROWS * D_MODEL / 4;
        split_rows_kernel<<<(unsigned)((n4 + 255) / 256), 256>>>(x, xhi, xlo, n4);
    }

    // 1) xz = x @ [in_w_f | in_w_b]   (M x 8192)
    hmma_gemm<<<dim3(EIGHT_E / 128, M_ROWS / 128), 256, GEMM_SMEM>>>(
        xhi, xlo, btin, p_xz, D_MODEL, D_MODEL, EIGHT_E);

    // 2) conv + silu, both dirs
    {
        size_t n = (size_t)M_ROWS * FOUR_E;
        conv_silu_kernel<<<(unsigned)((n + 255) / 256), 256>>>(
            P[0][1], P[0][2], P[1][1], P[1][2]);
    }

    // 3) proj per dir: xi_dir @ xproj_w_dir  (N=96)
    for (int dir = 0; dir < 2; dir++)
        hmma_gemm<<<dim3(1, M_ROWS / 128), 256, GEMM_SMEM>>>(
            xihi + dir * E_DIM, xilo + dir * E_DIM, btxp + (size_t)dir * 128 * E_DIM,
            p_proj + (size_t)dir * M_ROWS * PROJ_N, FOUR_E, E_DIM, PROJ_N);

    // 4) delta (both dirs)
    delta_kernel<<<dim3(2, M_ROWS / 8, 2), 256>>>(P[0][4], P[0][5], P[1][4], P[1][5]);

    // 5) selective scan (both dirs)
    scan_kernel<<<1024, 256>>>(P[0][6], P[1][6]);

    // 6) gate/combine (both dirs)
    {
        size_t n = (size_t)M_ROWS * FOUR_E;
        combine_kernel<<<(unsigned)((n + 255) / 256), 256>>>(P[0][7], P[1][7]);
    }

    // 7) out = [y_f | y_b] @ [out_w_f ; out_w_b]   (single GEMM, K=4096)
    hmma_gemm<<<dim3(D_MODEL / 128, M_ROWS / 128), 256, GEMM_SMEM>>>(
        yhi, ylo, btout, out, FOUR_E, FOUR_E, D_MODEL);
}

// round 7
// speedup vs baseline: 2.3100x; 1.0087x over previous
#include <cuda_runtime.h>
#include <cuda_fp16.h>
#include <math.h>
#include <stdint.h>

// ---------------------------------------------------------------------------
// BidirectionalMamba: D=1024, E=2048, N=16, dt_rank=64, B=4, L=2048.
// Both directions processed in ORIGINAL time order:
//   fwd: causal conv, forward scan.
//   bwd: anti-causal conv (flipped taps), backward scan.
// ---------------------------------------------------------------------------
#define D_MODEL  1024
#define E_DIM    2048
#define FOUR_E   4096
#define EIGHT_E  8192
#define N_ST     16
#define DT_RANK  64
#define PROJ_N   96
#define B_SZ     4
#define L_SEQ    2048
#define M_ROWS   8192

// ---------------------------------------------------------------------------
// Scratch (device globals)
// ---------------------------------------------------------------------------
__device__ float g_xz[(size_t)M_ROWS * EIGHT_E];
__device__ float g_xi[(size_t)M_ROWS * FOUR_E];
__device__ float g_delta[(size_t)M_ROWS * FOUR_E];
__device__ float g_proj[(size_t)2 * M_ROWS * PROJ_N];
__device__ float g_y[(size_t)M_ROWS * FOUR_E];

__device__ __half g_xhi[(size_t)M_ROWS * D_MODEL];
__device__ __half g_xlo[(size_t)M_ROWS * D_MODEL];
__device__ __half g_xihi[(size_t)M_ROWS * FOUR_E];
__device__ __half g_xilo[(size_t)M_ROWS * FOUR_E];
__device__ __half g_yhi[(size_t)M_ROWS * FOUR_E];
__device__ __half g_ylo[(size_t)M_ROWS * FOUR_E];
__device__ __half g_btin[(size_t)EIGHT_E * D_MODEL];
__device__ __half g_btxp[(size_t)2 * 128 * E_DIM];
__device__ __half g_btout[(size_t)D_MODEL * FOUR_E];

// ---------------------------------------------------------------------------
// helpers
// ---------------------------------------------------------------------------
__device__ __forceinline__ uint32_t smem_to_u32(const void* p)
{
    uint32_t a;
    asm("{ .reg .u64 t; cvta.to.shared.u64 t, %1; cvt.u32.u64 %0, t; }" : "=r"(a) : "l"(p));
    return a;
}

#define LDSM_X4(r, a) \
    asm volatile("ldmatrix.sync.aligned.m8n8.x4.shared.b16 {%0,%1,%2,%3}, [%4];" \
        : "=r"((r)[0]), "=r"((r)[1]), "=r"((r)[2]), "=r"((r)[3]) : "r"(a))

__device__ __forceinline__ void mma16816(float* d, const uint32_t* a, const uint32_t* b)
{
    asm volatile(
        "mma.sync.aligned.m16n8k16.row.col.f32.f16.f16.f32 "
        "{%0,%1,%2,%3}, {%4,%5,%6,%7}, {%8,%9}, {%0,%1,%2,%3};"
        : "+f"(d[0]), "+f"(d[1]), "+f"(d[2]), "+f"(d[3])
        : "r"(a[0]), "r"(a[1]), "r"(a[2]), "r"(a[3]), "r"(b[0]), "r"(b[1]));
}

#define CP_ASYNC16(dst, src) \
    asm volatile("cp.async.cg.shared.global [%0], [%1], 16;" :: "r"(dst), "l"(src))
#define CP_COMMIT()  asm volatile("cp.async.commit_group;" ::: "memory")
#define CP_WAIT(n)   asm volatile("cp.async.wait_group %0;" :: "n"(n) : "memory")

// ---------------------------------------------------------------------------
// 2-term split-fp16 HMMA GEMM: C[M,N] = (Ahi+Alo)[M,K] @ W[K,N], B = W^T hi.
// Block tile 128x128, BK=32, 256 threads (8 warps 2x4), warp tile 64x32.
// 3-stage cp.async pipeline, 2 CTAs/SM.  blockIdx.z batches independent
// problems via element offsets batchA/batchB/batchC.
// ---------------------------------------------------------------------------
#define ASTR_B      80
#define PLANE_B     (128 * ASTR_B)          // 10240
#define STAGE_B     (3 * PLANE_B)           // 30720 (Ahi, Alo, Bhi)
#define NSTAGE      3
#define GEMM_SMEM   (NSTAGE * STAGE_B)      // 92160

__device__ __forceinline__ void ld_plane(
    const __half* __restrict__ gsrc, int row0, int lda, int k0, char* stp, int tid)
{
#pragma unroll
    for (int j = 0; j < 2; j++) {
        int cid = j * 256 + tid;
        int r = cid >> 2;
        int c = cid & 3;
        const void* src = gsrc + (size_t)(row0 + r) * lda + k0 + c * 8;
        uint32_t dst = smem_to_u32(stp + r * ASTR_B + c * 16);
        CP_ASYNC16(dst, src);
    }
}

__global__ __launch_bounds__(256, 2) void hmma_gemm(
    const __half* __restrict__ Ahi, const __half* __restrict__ Alo,
    const __half* __restrict__ Bhi, float* __restrict__ C,
    int lda, int K, int Nc,
    size_t batchA, size_t batchB, size_t batchC)
{
    extern __shared__ char smem[];
    const int tid  = threadIdx.x;
    const int lane = tid & 31;
    const int warp = tid >> 5;
    const int wm   = warp & 1;
    const int wn   = warp >> 1;
    const int g    = lane >> 2;
    const int tg   = lane & 3;
    const int rowA = blockIdx.y * 128;
    const int rowB = blockIdx.x * 128;

    const __half* Ah = Ahi + blockIdx.z * batchA;
    const __half* Al = Alo + blockIdx.z * batchA;
    const __half* Bh = Bhi + blockIdx.z * batchB;
    float* Cz = C + blockIdx.z * batchC;

    float acc[4][4][4];
#pragma unroll
    for (int i = 0; i < 4; i++)
#pragma unroll
        for (int j = 0; j < 4; j++)
#pragma unroll
            for (int r = 0; r < 4; r++) acc[i][j][r] = 0.f;

    const int a_r = lane & 15;
    const int a_c = (lane >> 4) * 16;
    const int b_r = (lane & 7) + (((lane >> 4) & 1) << 3);
    const int b_c = ((lane >> 3) & 1) * 16;

    const int T = K >> 5;

    // prologue: stages 0 and 1
    {
        char* st = smem;
        ld_plane(Ah, rowA, lda, 0, st + 0 * PLANE_B, tid);
        ld_plane(Al, rowA, lda, 0, st + 1 * PLANE_B, tid);
        ld_plane(Bh, rowB, K,   0, st + 2 * PLANE_B, tid);
        CP_COMMIT();
        if (T > 1) {
            st = smem + STAGE_B;
            ld_plane(Ah, rowA, lda, 32, st + 0 * PLANE_B, tid);
            ld_plane(Al, rowA, lda, 32, st + 1 * PLANE_B, tid);
            ld_plane(Bh, rowB, K,   32, st + 2 * PLANE_B, tid);
            CP_COMMIT();
        }
    }

    int slot = 0;
    for (int t = 0; t < T; t++) {
        if (t + 2 < T) {
            int ns = (slot + 2) % NSTAGE;
            char* st = smem + ns * STAGE_B;
            const int k0 = (t + 2) << 5;
            ld_plane(Ah, rowA, lda, k0, st + 0 * PLANE_B, tid);
            ld_plane(Al, rowA, lda, k0, st + 1 * PLANE_B, tid);
            ld_plane(Bh, rowB, K,   k0, st + 2 * PLANE_B, tid);
            CP_COMMIT();
            CP_WAIT(2);
        } else if (t + 1 < T) {
            CP_WAIT(1);
        } else {
            CP_WAIT(0);
        }
        __syncthreads();

        char* st = smem + slot * STAGE_B;
        const uint32_t aB = smem_to_u32(st) + (wm * 64) * ASTR_B;
        const uint32_t bB = smem_to_u32(st) + 2 * PLANE_B + (wn * 32) * ASTR_B;

#pragma unroll
        for (int s = 0; s < 2; s++) {
            const int koff = s * 32;
            uint32_t ahi[4][4], alo[4][4];
#pragma unroll
            for (int mt = 0; mt < 4; mt++) {
                uint32_t addr = aB + (mt * 16 + a_r) * ASTR_B + a_c + koff;
                LDSM_X4(ahi[mt], addr);
                LDSM_X4(alo[mt], addr + PLANE_B);
            }
#pragma unroll
            for (int np = 0; np < 2; np++) {
                uint32_t baddr = bB + (np * 16 + b_r) * ASTR_B + b_c + koff;
                uint32_t bh[4];
                LDSM_X4(bh, baddr);
#pragma unroll
                for (int mt = 0; mt < 4; mt++) {
                    mma16816(acc[mt][np * 2 + 0], ahi[mt], bh + 0);
                    mma16816(acc[mt][np * 2 + 0], alo[mt], bh + 0);
                    mma16816(acc[mt][np * 2 + 1], ahi[mt], bh + 2);
                    mma16816(acc[mt][np * 2 + 1], alo[mt], bh + 2);
                }
            }
        }
        __syncthreads();
        slot = (slot + 1) % NSTAGE;
    }

#pragma unroll
    for (int mt = 0; mt < 4; mt++) {
#pragma unroll
        for (int half = 0; half < 2; half++) {
            int gr = blockIdx.y * 128 + wm * 64 + mt * 16 + g + half * 8;
            float* crow = Cz + (size_t)gr * Nc;
#pragma unroll
            for (int nt = 0; nt < 4; nt++) {
                int gc = blockIdx.x * 128 + wn * 32 + nt * 8 + tg * 2;
                if (gc + 1 < Nc) {
                    crow[gc]     = acc[mt][nt][half * 2 + 0];
                    crow[gc + 1] = acc[mt][nt][half * 2 + 1];
                }
            }
        }
    }
}

// ---------------------------------------------------------------------------
// fp16 split helpers / prep kernels
// ---------------------------------------------------------------------------
__device__ __forceinline__ void hsplit(float v, __half& h, __half& l)
{
    h = __float2half(v);
    l = __float2half(v - __half2float(h));
}

__global__ __launch_bounds__(256) void split_rows_kernel(
    const float* __restrict__ in, __half* __restrict__ hi, __half* __restrict__ lo, size_t n4)
{
    size_t i = (size_t)blockIdx.x * blockDim.x + threadIdx.x;
    if (i >= n4) return;
    float4 v = ((const float4*)in)[i];
    __half h0, l0, h1, l1, h2, l2, h3, l3;
    hsplit(v.x, h0, l0); hsplit(v.y, h1, l1); hsplit(v.z, h2, l2); hsplit(v.w, h3, l3);
    ((__half2*)hi)[i * 2 + 0] = __halves2half2(h0, h1);
    ((__half2*)hi)[i * 2 + 1] = __halves2half2(h2, h3);
    ((__half2*)lo)[i * 2 + 0] = __halves2half2(l0, l1);
    ((__half2*)lo)[i * 2 + 1] = __halves2half2(l2, l3);
}

__global__ void transpose_h_kernel(
    const float* __restrict__ W, __half* __restrict__ bh, int Ktot, int koff, int Nv)
{
    __shared__ float t[32][33];
    const int n0 = blockIdx.x * 32, k0 = blockIdx.y * 32;
    const int tx = threadIdx.x, ty = threadIdx.y;
#pragma unroll
    for (int i = 0; i < 32; i += 8) {
        int n = n0 + tx;
        t[ty + i][tx] = (n < Nv) ? W[(size_t)(k0 + ty + i) * Nv + n] : 0.f;
    }
    __syncthreads();
#pragma unroll
    for (int i = 0; i < 32; i += 8) {
        int n = n0 + ty + i, k = k0 + tx;
        bh[(size_t)n * Ktot + koff + k] = __float2half(t[tx][ty + i]);
    }
}

// ---------------------------------------------------------------------------
// Depthwise conv1d (D_CONV=4) + SiLU, both directions in one pass.
// ---------------------------------------------------------------------------
__global__ __launch_bounds__(256) void conv_silu_kernel(
    const float* __restrict__ cwf, const float* __restrict__ cbf,
    const float* __restrict__ cwb, const float* __restrict__ cbb)
{
    size_t idx = (size_t)blockIdx.x * blockDim.x + threadIdx.x;
    if (idx >= (size_t)M_ROWS * FOUR_E) return;
    const int c = (int)(idx & (FOUR_E - 1));
    const int m = (int)(idx >> 12);
    const int dir = c >> 11;
    const int e = c & (E_DIM - 1);
    const int l = m & (L_SEQ - 1);

    const float* cw = dir ? cwb : cwf;
    const float* cb = dir ? cbb : cbf;
    const float* src = g_xz + (size_t)m * EIGHT_E + dir * 4096 + e;

    float acc = cb[e];
#pragma unroll
    for (int t = 0; t < 4; t++) {
        int off  = dir ? t : t - 3;
        int widx = dir ? 3 - t : t;
        int ll = l + off;
        if (ll >= 0 && ll < L_SEQ)
            acc = fmaf(src[(ptrdiff_t)off * EIGHT_E], cw[e * 4 + widx], acc);
    }
    float v = acc / (1.f + __expf(-acc));
    g_xi[idx] = v;
    __half h, lo;
    hsplit(v, h, lo);
    g_xihi[idx] = h;
    g_xilo[idx] = lo;
}

// ---------------------------------------------------------------------------
// delta = softplus( proj[:, :64] @ dt_w + dt_b );  8 m-rows per block.
// ---------------------------------------------------------------------------
__device__ __forceinline__ float softplusf(float x)
{
    return (x > 20.f) ? x : log1pf(__expf(x));
}

__global__ __launch_bounds__(256) void delta_kernel(
    const float* __restrict__ dtw_f, const float* __restrict__ dtb_f,
    const float* __restrict__ dtw_b, const float* __restrict__ dtb_b)
{
    __shared__ float s[8][DT_RANK];
    const int dir = blockIdx.z;
    const float* dtw = dir ? dtw_b : dtw_f;
    const float* dtb = dir ? dtb_b : dtb_f;
    const int m0 = blockIdx.y * 8;
    const int col = blockIdx.x * 1024 + threadIdx.x * 4;

    const float* pbase = g_proj + (size_t)dir * M_ROWS * PROJ_N;
#pragma unroll
    for (int i = threadIdx.x; i < 8 * DT_RANK; i += 256) {
        int row = i >> 6, r = i & 63;
        s[row][r] = pbase[(size_t)(m0 + row) * PROJ_N + r];
    }
    __syncthreads();

    float4 bias = *(const float4*)(dtb + col);
    float4 acc[8];
#pragma unroll
    for (int row = 0; row < 8; row++) acc[row] = bias;

#pragma unroll 4
    for (int r = 0; r < DT_RANK; r++) {
        float4 w = *(const float4*)(dtw + (size_t)r * E_DIM + col);
#pragma unroll
        for (int row = 0; row < 8; row++) {
            float sv = s[row][r];
            acc[row].x = fmaf(sv, w.x, acc[row].x);
            acc[row].y = fmaf(sv, w.y, acc[row].y);
            acc[row].z = fmaf(sv, w.z, acc[row].z);
            acc[row].w = fmaf(sv, w.w, acc[row].w);
        }
    }
#pragma unroll
    for (int row = 0; row < 8; row++) {
        float4 o;
        o.x = softplusf(acc[row].x);
        o.y = softplusf(acc[row].y);
        o.z = softplusf(acc[row].z);
        o.w = softplusf(acc[row].w);
        *(float4*)(g_delta + (size_t)(m0 + row) * FOUR_E + dir * E_DIM + col) = o;
    }
}

// ---------------------------------------------------------------------------
// Selective scan, both directions.
// ---------------------------------------------------------------------------
__global__ __launch_bounds__(256) void scan_kernel(
    const float* __restrict__ Alog_f, const float* __restrict__ Alog_b)
{
    const int lane = threadIdx.x & 31;
    const int w = blockIdx.x * (blockDim.x >> 5) + (threadIdx.x >> 5);
    const int half = lane >> 4;
    const int n = lane & 15;
    const int chain = 2 * w + half;
    const int dir = chain >> 13;
    const int b = (chain >> 11) & 3;
    const int e = chain & (E_DIM - 1);
    const int col = dir * E_DIM + e;

    const float* Al = dir ? Alog_b : Alog_f;
    const float a = -__expf(Al[e * N_ST + n]);
    const float a0 = __shfl_sync(0xffffffffu, a, lane & 16);
    const float kf = rintf(a / a0);
    const int k = (int)kf;
    const bool ok = (fabsf(a - kf * a0) <= 1e-5f * fmaxf(fabsf(a), 1e-20f)) &&
                    (k >= 1) && (k <= 16);
    const bool fast = __all_sync(0xffffffffu, ok);

    const int l0 = dir ? (L_SEQ - 1) : 0;
    const ptrdiff_t strideE = dir ? -FOUR_E : FOUR_E;
    const ptrdiff_t strideP = dir ? -PROJ_N : PROJ_N;

    const float* dp = g_delta + (size_t)(b * L_SEQ + l0) * FOUR_E + col;
    const float* up = g_xi    + (size_t)(b * L_SEQ + l0) * FOUR_E + col;
    const float* pp = g_proj  + (size_t)dir * M_ROWS * PROJ_N
                             + (size_t)(b * L_SEQ + l0) * PROJ_N;
    float*       yp = g_y     + (size_t)(b * L_SEQ + l0) * FOUR_E + col;

    float h = 0.f;
    float d  = dp[0];
    float u  = up[0];
    float Bv = pp[64 + n];
    float Cv = pp[80 + n];

    for (int i = 0; i < L_SEQ; i++) {
        float dn = 0.f, un = 0.f, Bn = 0.f, Cn = 0.f;
        if (i + 1 < L_SEQ) {
            dn = dp[strideE];
            un = up[strideE];
            Bn = pp[strideP + 64 + n];
            Cn = pp[strideP + 80 + n];
        }

        float decay;
        if (fast) {
            float p = __expf(d * a0);
            float p2 = p * p, p4 = p2 * p2, p8 = p4 * p4;
            decay = 1.f;
            if (k & 1)  decay *= p;
            if (k & 2)  decay *= p2;
            if (k & 4)  decay *= p4;
            if (k & 8)  decay *= p8;
            if (k & 16) decay *= p8 * p8;
        } else {
            decay = __expf(d * a);
        }

        h = fmaf(decay, h, d * u * Bv);

        float v = h * Cv;
        v += __shfl_xor_sync(0xffffffffu, v, 1);
        v += __shfl_xor_sync(0xffffffffu, v, 2);
        v += __shfl_xor_sync(0xffffffffu, v, 4);
        v += __shfl_xor_sync(0xffffffffu, v, 8);
        if (n == 0) *yp = v;

        dp += strideE; up += strideE; yp += strideE; pp += strideP;
        d = dn; u = un; Bv = Bn; Cv = Cn;
    }
}

// ---------------------------------------------------------------------------
// y = (y_scan + xi*Dp) * silu(z) -> fp16 hi/lo planes (both dirs)
// ---------------------------------------------------------------------------
__global__ __launch_bounds__(256) void combine_kernel(
    const float* __restrict__ Dp_f, const float* __restrict__ Dp_b)
{
    size_t idx = (size_t)blockIdx.x * blockDim.x + threadIdx.x;
    if (idx >= (size_t)M_ROWS * FOUR_E) return;
    const int c = (int)(idx & (FOUR_E - 1));
    const size_t m = idx >> 12;
    const int dir = c >> 11;
    const int e = c & (E_DIM - 1);
    const float* Dp = dir ? Dp_b : Dp_f;

    float z = g_xz[m * EIGHT_E + dir * 4096 + 2048 + e];
    float sz = z / (1.f + __expf(-z));
    float v = (g_y[idx] + g_xi[idx] * Dp[e]) * sz;
    __half h, lo;
    hsplit(v, h, lo);
    g_yhi[idx] = h;
    g_ylo[idx] = lo;
}

// ---------------------------------------------------------------------------
// Launcher
// ---------------------------------------------------------------------------
extern "C" void kernel_launch(void* const* d_in, const int* in_sizes, int n_in,
                              void* d_out, int out_size)
{
    (void)in_sizes; (void)n_in; (void)out_size;
    const float* x = (const float*)d_in[0];
    float* out = (float*)d_out;

    cudaFuncSetAttribute(hmma_gemm, cudaFuncAttributeMaxDynamicSharedMemorySize, GEMM_SMEM);

    const float* P[2][9];
    for (int dir = 0; dir < 2; dir++)
        for (int j = 0; j < 9; j++)
            P[dir][j] = (const float*)d_in[1 + dir * 9 + j];

    __half *xhi, *xlo, *xihi, *xilo, *yhi, *ylo, *btin, *btxp, *btout;
    float *p_xz, *p_proj;
    cudaGetSymbolAddress((void**)&xhi, g_xhi);
    cudaGetSymbolAddress((void**)&xlo, g_xlo);
    cudaGetSymbolAddress((void**)&xihi, g_xihi);
    cudaGetSymbolAddress((void**)&xilo, g_xilo);
    cudaGetSymbolAddress((void**)&yhi, g_yhi);
    cudaGetSymbolAddress((void**)&ylo, g_ylo);
    cudaGetSymbolAddress((void**)&btin, g_btin);
    cudaGetSymbolAddress((void**)&btxp, g_btxp);
    cudaGetSymbolAddress((void**)&btout, g_btout);
    cudaGetSymbolAddress((void**)&p_xz, g_xz);
    cudaGetSymbolAddress((void**)&p_proj, g_proj);

    // ---- weight prep ----
    transpose_h_kernel<<<dim3(128, 32), dim3(32, 8)>>>(P[0][0], btin, D_MODEL, 0, 4096);
    transpose_h_kernel<<<dim3(128, 32), dim3(32, 8)>>>(
        P[1][0], btin + (size_t)4096 * D_MODEL, D_MODEL, 0, 4096);
    for (int dir = 0; dir < 2; dir++)
        transpose_h_kernel<<<dim3(4, 64), dim3(32, 8)>>>(
            P[dir][3], btxp + (size_t)dir * 128 * E_DIM, E_DIM, 0, PROJ_N);
    transpose_h_kernel<<<dim3(32, 64), dim3(32, 8)>>>(P[0][8], btout, FOUR_E, 0, D_MODEL);
    transpose_h_kernel<<<dim3(32, 64), dim3(32, 8)>>>(P[1][8], btout, FOUR_E, 2048, D_MODEL);

    // ---- split x ----
    {
        size_t n4 = (size_t)M_ROWS * D_MODEL / 4;
        split_rows_kernel<<<(unsigned)((n4 + 255) / 256), 256>>>(x, xhi, xlo, n4);
    }

    // 1) xz = x @ [in_w_f | in_w_b]
    hmma_gemm<<<dim3(EIGHT_E / 128, M_ROWS / 128, 1), 256, GEMM_SMEM>>>(
        xhi, xlo, btin, p_xz, D_MODEL, D_MODEL, EIGHT_E, 0, 0, 0);

    // 2) conv + silu, both dirs
    {
        size_t n = (size_t)M_ROWS * FOUR_E;
        conv_silu_kernel<<<(unsigned)((n + 255) / 256), 256>>>(
            P[0][1], P[0][2], P[1][1], P[1][2]);
    }

    // 3) proj: both dirs batched via blockIdx.z
    hmma_gemm<<<dim3(1, M_ROWS / 128, 2), 256, GEMM_SMEM>>>(
        xihi, xilo, btxp, p_proj, FOUR_E, E_DIM, PROJ_N,
        (size_t)E_DIM, (size_t)128 * E_DIM, (size_t)M_ROWS * PROJ_N);

    // 4) delta (both dirs)
    delta_kernel<<<dim3(2, M_ROWS / 8, 2), 256>>>(P[0][4], P[0][5], P[1][4], P[1][5]);

    // 5) selective scan (both dirs)
    scan_kernel<<<1024, 256>>>(P[0][6], P[1][6]);

    // 6) gate/combine (both dirs)
    {
        size_t n = (size_t)M_ROWS * FOUR_E;
        combine_kernel<<<(unsigned)((n + 255) / 256), 256>>>(P[0][7], P[1][7]);
    }

    // 7) out = [y_f | y_b] @ [out_w_f ; out_w_b]
    hmma_gemm<<<dim3(D_MODEL / 128, M_ROWS / 128, 1), 256, GEMM_SMEM>>>(
        yhi, ylo, btout, out, FOUR_E, FOUR_E, D_MODEL, 0, 0, 0);
}

// round 8
// speedup vs baseline: 3.0516x; 1.3210x over previous
#include <cuda_runtime.h>
#include <cuda_fp16.h>
#include <math.h>
#include <stdint.h>

// ---------------------------------------------------------------------------
// BidirectionalMamba: D=1024, E=2048, N=16, dt_rank=64, B=4, L=2048.
// fwd: causal conv + forward scan.  bwd: anti-causal conv + backward scan.
// ---------------------------------------------------------------------------
#define D_MODEL  1024
#define E_DIM    2048
#define FOUR_E   4096
#define EIGHT_E  8192
#define N_ST     16
#define DT_RANK  64
#define PROJ_N   96
#define B_SZ     4
#define L_SEQ    2048
#define M_ROWS   8192

__device__ float g_xz[(size_t)M_ROWS * EIGHT_E];
__device__ float g_xi[(size_t)M_ROWS * FOUR_E];
__device__ float g_delta[(size_t)M_ROWS * FOUR_E];
__device__ float g_proj[(size_t)2 * M_ROWS * PROJ_N];
__device__ float g_y[(size_t)M_ROWS * FOUR_E];

__device__ __half g_xhi[(size_t)M_ROWS * D_MODEL];
__device__ __half g_xlo[(size_t)M_ROWS * D_MODEL];
__device__ __half g_xihi[(size_t)M_ROWS * FOUR_E];
__device__ __half g_xilo[(size_t)M_ROWS * FOUR_E];
__device__ __half g_yhi[(size_t)M_ROWS * FOUR_E];
__device__ __half g_ylo[(size_t)M_ROWS * FOUR_E];
__device__ __half g_btin[(size_t)EIGHT_E * D_MODEL];
__device__ __half g_btxp[(size_t)2 * 128 * E_DIM];
__device__ __half g_btout[(size_t)D_MODEL * FOUR_E];

// ---------------------------------------------------------------------------
// helpers
// ---------------------------------------------------------------------------
__device__ __forceinline__ uint32_t smem_to_u32(const void* p)
{
    uint32_t a;
    asm("{ .reg .u64 t; cvta.to.shared.u64 t, %1; cvt.u32.u64 %0, t; }" : "=r"(a) : "l"(p));
    return a;
}

#define LDSM_X4(r, a) \
    asm volatile("ldmatrix.sync.aligned.m8n8.x4.shared.b16 {%0,%1,%2,%3}, [%4];" \
        : "=r"((r)[0]), "=r"((r)[1]), "=r"((r)[2]), "=r"((r)[3]) : "r"(a))

__device__ __forceinline__ void mma16816(float* d, const uint32_t* a, const uint32_t* b)
{
    asm volatile(
        "mma.sync.aligned.m16n8k16.row.col.f32.f16.f16.f32 "
        "{%0,%1,%2,%3}, {%4,%5,%6,%7}, {%8,%9}, {%0,%1,%2,%3};"
        : "+f"(d[0]), "+f"(d[1]), "+f"(d[2]), "+f"(d[3])
        : "r"(a[0]), "r"(a[1]), "r"(a[2]), "r"(a[3]), "r"(b[0]), "r"(b[1]));
}

#define CP_ASYNC16(dst, src) \
    asm volatile("cp.async.cg.shared.global [%0], [%1], 16;" :: "r"(dst), "l"(src))
#define CP_COMMIT()  asm volatile("cp.async.commit_group;" ::: "memory")
#define CP_WAIT(n)   asm volatile("cp.async.wait_group %0;" :: "n"(n) : "memory")

// ---------------------------------------------------------------------------
// 2-term split-fp16 HMMA GEMM (128x128 tile, BK=32, 8 warps 2x4, warp 64x32,
// 3-stage cp.async ring, ONE barrier per k-tile).
// ---------------------------------------------------------------------------
#define ASTR_B      80
#define PLANE_B     (128 * ASTR_B)
#define STAGE_B     (3 * PLANE_B)
#define NSTAGE      3
#define GEMM_SMEM   (NSTAGE * STAGE_B)

__device__ __forceinline__ void ld_plane(
    const __half* __restrict__ gsrc, int row0, int lda, int k0, char* stp, int tid)
{
#pragma unroll
    for (int j = 0; j < 2; j++) {
        int cid = j * 256 + tid;
        int r = cid >> 2;
        int c = cid & 3;
        const void* src = gsrc + (size_t)(row0 + r) * lda + k0 + c * 8;
        uint32_t dst = smem_to_u32(stp + r * ASTR_B + c * 16);
        CP_ASYNC16(dst, src);
    }
}

__global__ __launch_bounds__(256, 2) void hmma_gemm(
    const __half* __restrict__ Ahi, const __half* __restrict__ Alo,
    const __half* __restrict__ Bhi, float* __restrict__ C,
    int lda, int K, int Nc,
    size_t batchA, size_t batchB, size_t batchC)
{
    extern __shared__ char smem[];
    const int tid  = threadIdx.x;
    const int lane = tid & 31;
    const int warp = tid >> 5;
    const int wm   = warp & 1;
    const int wn   = warp >> 1;
    const int g    = lane >> 2;
    const int tg   = lane & 3;
    const int rowA = blockIdx.y * 128;
    const int rowB = blockIdx.x * 128;

    const __half* Ah = Ahi + blockIdx.z * batchA;
    const __half* Al = Alo + blockIdx.z * batchA;
    const __half* Bh = Bhi + blockIdx.z * batchB;
    float* Cz = C + blockIdx.z * batchC;

    float acc[4][4][4];
#pragma unroll
    for (int i = 0; i < 4; i++)
#pragma unroll
        for (int j = 0; j < 4; j++)
#pragma unroll
            for (int r = 0; r < 4; r++) acc[i][j][r] = 0.f;

    const int a_r = lane & 15;
    const int a_c = (lane >> 4) * 16;
    const int b_r = (lane & 7) + (((lane >> 4) & 1) << 3);
    const int b_c = ((lane >> 3) & 1) * 16;

    const int T = K >> 5;

    // prologue: stages 0 and 1
    {
        char* st = smem;
        ld_plane(Ah, rowA, lda, 0, st + 0 * PLANE_B, tid);
        ld_plane(Al, rowA, lda, 0, st + 1 * PLANE_B, tid);
        ld_plane(Bh, rowB, K,   0, st + 2 * PLANE_B, tid);
        CP_COMMIT();
        if (T > 1) {
            st = smem + STAGE_B;
            ld_plane(Ah, rowA, lda, 32, st + 0 * PLANE_B, tid);
            ld_plane(Al, rowA, lda, 32, st + 1 * PLANE_B, tid);
            ld_plane(Bh, rowB, K,   32, st + 2 * PLANE_B, tid);
            CP_COMMIT();
        }
    }

    int slot = 0;
    for (int t = 0; t < T; t++) {
        if (t + 1 < T) { CP_WAIT(1); } else { CP_WAIT(0); }
        __syncthreads();

        if (t + 2 < T) {
            int ns = slot - 1; if (ns < 0) ns += NSTAGE;   // (slot+2)%3
            char* st = smem + ns * STAGE_B;
            const int k0 = (t + 2) << 5;
            ld_plane(Ah, rowA, lda, k0, st + 0 * PLANE_B, tid);
            ld_plane(Al, rowA, lda, k0, st + 1 * PLANE_B, tid);
            ld_plane(Bh, rowB, K,   k0, st + 2 * PLANE_B, tid);
            CP_COMMIT();
        }

        char* st = smem + slot * STAGE_B;
        const uint32_t aB = smem_to_u32(st) + (wm * 64) * ASTR_B;
        const uint32_t bB = smem_to_u32(st) + 2 * PLANE_B + (wn * 32) * ASTR_B;

#pragma unroll
        for (int s = 0; s < 2; s++) {
            const int koff = s * 32;
            uint32_t ahi[4][4], alo[4][4];
#pragma unroll
            for (int mt = 0; mt < 4; mt++) {
                uint32_t addr = aB + (mt * 16 + a_r) * ASTR_B + a_c + koff;
                LDSM_X4(ahi[mt], addr);
                LDSM_X4(alo[mt], addr + PLANE_B);
            }
#pragma unroll
            for (int np = 0; np < 2; np++) {
                uint32_t baddr = bB + (np * 16 + b_r) * ASTR_B + b_c + koff;
                uint32_t bh[4];
                LDSM_X4(bh, baddr);
#pragma unroll
                for (int mt = 0; mt < 4; mt++) {
                    mma16816(acc[mt][np * 2 + 0], ahi[mt], bh + 0);
                    mma16816(acc[mt][np * 2 + 0], alo[mt], bh + 0);
                    mma16816(acc[mt][np * 2 + 1], ahi[mt], bh + 2);
                    mma16816(acc[mt][np * 2 + 1], alo[mt], bh + 2);
                }
            }
        }
        slot++; if (slot == NSTAGE) slot = 0;
    }

#pragma unroll
    for (int mt = 0; mt < 4; mt++) {
#pragma unroll
        for (int half = 0; half < 2; half++) {
            int gr = blockIdx.y * 128 + wm * 64 + mt * 16 + g + half * 8;
            float* crow = Cz + (size_t)gr * Nc;
#pragma unroll
            for (int nt = 0; nt < 4; nt++) {
                int gc = blockIdx.x * 128 + wn * 32 + nt * 8 + tg * 2;
                if (gc + 1 < Nc) {
                    crow[gc]     = acc[mt][nt][half * 2 + 0];
                    crow[gc + 1] = acc[mt][nt][half * 2 + 1];
                }
            }
        }
    }
}

// ---------------------------------------------------------------------------
// fp16 split helpers / prep kernels
// ---------------------------------------------------------------------------
__device__ __forceinline__ void hsplit(float v, __half& h, __half& l)
{
    h = __float2half(v);
    l = __float2half(v - __half2float(h));
}

__global__ __launch_bounds__(256) void split_rows_kernel(
    const float* __restrict__ in, __half* __restrict__ hi, __half* __restrict__ lo, size_t n4)
{
    size_t i = (size_t)blockIdx.x * blockDim.x + threadIdx.x;
    if (i >= n4) return;
    float4 v = ((const float4*)in)[i];
    __half h0, l0, h1, l1, h2, l2, h3, l3;
    hsplit(v.x, h0, l0); hsplit(v.y, h1, l1); hsplit(v.z, h2, l2); hsplit(v.w, h3, l3);
    ((__half2*)hi)[i * 2 + 0] = __halves2half2(h0, h1);
    ((__half2*)hi)[i * 2 + 1] = __halves2half2(h2, h3);
    ((__half2*)lo)[i * 2 + 0] = __halves2half2(l0, l1);
    ((__half2*)lo)[i * 2 + 1] = __halves2half2(l2, l3);
}

__global__ void transpose_h_kernel(
    const float* __restrict__ W, __half* __restrict__ bh, int Ktot, int koff, int Nv)
{
    __shared__ float t[32][33];
    const int n0 = blockIdx.x * 32, k0 = blockIdx.y * 32;
    const int tx = threadIdx.x, ty = threadIdx.y;
#pragma unroll
    for (int i = 0; i < 32; i += 8) {
        int n = n0 + tx;
        t[ty + i][tx] = (n < Nv) ? W[(size_t)(k0 + ty + i) * Nv + n] : 0.f;
    }
    __syncthreads();
#pragma unroll
    for (int i = 0; i < 32; i += 8) {
        int n = n0 + ty + i, k = k0 + tx;
        bh[(size_t)n * Ktot + koff + k] = __float2half(t[tx][ty + i]);
    }
}

// ---------------------------------------------------------------------------
// Depthwise conv1d (D_CONV=4) + SiLU, both directions in one pass.
// ---------------------------------------------------------------------------
__global__ __launch_bounds__(256) void conv_silu_kernel(
    const float* __restrict__ cwf, const float* __restrict__ cbf,
    const float* __restrict__ cwb, const float* __restrict__ cbb)
{
    size_t idx = (size_t)blockIdx.x * blockDim.x + threadIdx.x;
    if (idx >= (size_t)M_ROWS * FOUR_E) return;
    const int c = (int)(idx & (FOUR_E - 1));
    const int m = (int)(idx >> 12);
    const int dir = c >> 11;
    const int e = c & (E_DIM - 1);
    const int l = m & (L_SEQ - 1);

    const float* cw = dir ? cwb : cwf;
    const float* cb = dir ? cbb : cbf;
    const float* src = g_xz + (size_t)m * EIGHT_E + dir * 4096 + e;

    float acc = cb[e];
#pragma unroll
    for (int t = 0; t < 4; t++) {
        int off  = dir ? t : t - 3;
        int widx = dir ? 3 - t : t;
        int ll = l + off;
        if (ll >= 0 && ll < L_SEQ)
            acc = fmaf(src[(ptrdiff_t)off * EIGHT_E], cw[e * 4 + widx], acc);
    }
    float v = acc / (1.f + __expf(-acc));
    g_xi[idx] = v;
    __half h, lo;
    hsplit(v, h, lo);
    g_xihi[idx] = h;
    g_xilo[idx] = lo;
}

// ---------------------------------------------------------------------------
// delta = softplus( proj[:, :64] @ dt_w + dt_b );  16 m-rows per block.
// ---------------------------------------------------------------------------
__device__ __forceinline__ float softplusf(float x)
{
    return (x > 20.f) ? x : log1pf(__expf(x));
}

__global__ __launch_bounds__(256) void delta_kernel(
    const float* __restrict__ dtw_f, const float* __restrict__ dtb_f,
    const float* __restrict__ dtw_b, const float* __restrict__ dtb_b)
{
    __shared__ float s[16][DT_RANK];
    const int dir = blockIdx.z;
    const float* dtw = dir ? dtw_b : dtw_f;
    const float* dtb = dir ? dtb_b : dtb_f;
    const int m0 = blockIdx.y * 16;
    const int col = blockIdx.x * 1024 + threadIdx.x * 4;

    const float* pbase = g_proj + (size_t)dir * M_ROWS * PROJ_N;
#pragma unroll
    for (int i = threadIdx.x; i < 16 * DT_RANK; i += 256) {
        int row = i >> 6, r = i & 63;
        s[row][r] = pbase[(size_t)(m0 + row) * PROJ_N + r];
    }
    __syncthreads();

    float4 bias = *(const float4*)(dtb + col);
    float4 acc[16];
#pragma unroll
    for (int row = 0; row < 16; row++) acc[row] = bias;

#pragma unroll 2
    for (int r = 0; r < DT_RANK; r++) {
        float4 w = *(const float4*)(dtw + (size_t)r * E_DIM + col);
#pragma unroll
        for (int row = 0; row < 16; row++) {
            float sv = s[row][r];
            acc[row].x = fmaf(sv, w.x, acc[row].x);
            acc[row].y = fmaf(sv, w.y, acc[row].y);
            acc[row].z = fmaf(sv, w.z, acc[row].z);
            acc[row].w = fmaf(sv, w.w, acc[row].w);
        }
    }
#pragma unroll
    for (int row = 0; row < 16; row++) {
        float4 o;
        o.x = softplusf(acc[row].x);
        o.y = softplusf(acc[row].y);
        o.z = softplusf(acc[row].z);
        o.w = softplusf(acc[row].w);
        *(float4*)(g_delta + (size_t)(m0 + row) * FOUR_E + dir * E_DIM + col) = o;
    }
}

// ---------------------------------------------------------------------------
// Selective scan: 4 lanes per chain (4 states each), 8 chains per warp.
// Fast path (verified): A[e,n] = (n+1)*A[e,0]  ->  decay_n = pb^(n+1),
// pb = exp(delta*A0): 1 exp + power ladder.  Fallback: 4 exps per lane.
// ---------------------------------------------------------------------------
__global__ __launch_bounds__(256) void scan_kernel(
    const float* __restrict__ Alog_f, const float* __restrict__ Alog_b)
{
    const int lane = threadIdx.x & 31;
    const int wglob = blockIdx.x * 8 + (threadIdx.x >> 5);
    const int t = lane & 3;                    // lane within chain
    const int chain = wglob * 8 + (lane >> 2); // 0..16383
    const int dir = chain >> 13;
    const int b = (chain >> 11) & 3;
    const int e = chain & (E_DIM - 1);
    const int col = dir * E_DIM + e;
    const int n0 = t * 4;

    const float* Al = dir ? Alog_b : Alog_f;
    float a[4];
#pragma unroll
    for (int j = 0; j < 4; j++) a[j] = -__expf(Al[e * N_ST + n0 + j]);
    const float a0 = __shfl_sync(0xffffffffu, a[0], lane & ~3);

    bool ok = true;
#pragma unroll
    for (int j = 0; j < 4; j++) {
        float expect = (float)(n0 + j + 1) * a0;
        ok = ok && (fabsf(a[j] - expect) <= 1e-5f * fmaxf(fabsf(a[j]), 1e-20f));
    }
    const bool fast = __all_sync(0xffffffffu, ok);

    const int l0 = dir ? (L_SEQ - 1) : 0;
    const ptrdiff_t strideE = dir ? -FOUR_E : FOUR_E;
    const ptrdiff_t strideP = dir ? -PROJ_N : PROJ_N;

    const float* dp = g_delta + (size_t)(b * L_SEQ + l0) * FOUR_E + col;
    const float* up = g_xi    + (size_t)(b * L_SEQ + l0) * FOUR_E + col;
    const float* pp = g_proj  + (size_t)dir * M_ROWS * PROJ_N
                             + (size_t)(b * L_SEQ + l0) * PROJ_N;
    float*       yp = g_y     + (size_t)(b * L_SEQ + l0) * FOUR_E + col;

    float h0 = 0.f, h1 = 0.f, h2 = 0.f, h3 = 0.f;
    float d = dp[0];
    float u = up[0];
    float4 Bv = *(const float4*)(pp + 64 + n0);
    float4 Cv = *(const float4*)(pp + 80 + n0);

    for (int i = 0; i < L_SEQ; i++) {
        float dn = 0.f, un = 0.f;
        float4 Bn = make_float4(0.f, 0.f, 0.f, 0.f);
        float4 Cn = Bn;
        if (i + 1 < L_SEQ) {
            dn = dp[strideE];
            un = up[strideE];
            Bn = *(const float4*)(pp + strideP + 64 + n0);
            Cn = *(const float4*)(pp + strideP + 80 + n0);
        }

        float d0, d1, d2, d3;
        if (fast) {
            float pb = __expf(d * a0);
            float p2 = pb * pb;
            float p4 = p2 * p2;
            float p8 = p4 * p4;
            float sel = (t == 0) ? 1.f : (t == 1) ? p4 : (t == 2) ? p8 : p8 * p4;
            d0 = sel * pb;
            d1 = d0 * pb;
            d2 = d1 * pb;
            d3 = d2 * pb;
        } else {
            d0 = __expf(d * a[0]);
            d1 = __expf(d * a[1]);
            d2 = __expf(d * a[2]);
            d3 = __expf(d * a[3]);
        }

        const float du = d * u;
        h0 = fmaf(d0, h0, du * Bv.x);
        h1 = fmaf(d1, h1, du * Bv.y);
        h2 = fmaf(d2, h2, du * Bv.z);
        h3 = fmaf(d3, h3, du * Bv.w);

        float v = h0 * Cv.x;
        v = fmaf(h1, Cv.y, v);
        v = fmaf(h2, Cv.z, v);
        v = fmaf(h3, Cv.w, v);
        v += __shfl_xor_sync(0xffffffffu, v, 1);
        v += __shfl_xor_sync(0xffffffffu, v, 2);
        if (t == 0) *yp = v;

        dp += strideE; up += strideE; yp += strideE; pp += strideP;
        d = dn; u = un; Bv = Bn; Cv = Cn;
    }
}

// ---------------------------------------------------------------------------
// y = (y_scan + xi*Dp) * silu(z) -> fp16 hi/lo planes (both dirs)
// ---------------------------------------------------------------------------
__global__ __launch_bounds__(256) void combine_kernel(
    const float* __restrict__ Dp_f, const float* __restrict__ Dp_b)
{
    size_t idx = (size_t)blockIdx.x * blockDim.x + threadIdx.x;
    if (idx >= (size_t)M_ROWS * FOUR_E) return;
    const int c = (int)(idx & (FOUR_E - 1));
    const size_t m = idx >> 12;
    const int dir = c >> 11;
    const int e = c & (E_DIM - 1);
    const float* Dp = dir ? Dp_b : Dp_f;

    float z = g_xz[m * EIGHT_E + dir * 4096 + 2048 + e];
    float sz = z / (1.f + __expf(-z));
    float v = (g_y[idx] + g_xi[idx] * Dp[e]) * sz;
    __half h, lo;
    hsplit(v, h, lo);
    g_yhi[idx] = h;
    g_ylo[idx] = lo;
}

// ---------------------------------------------------------------------------
// Launcher
// ---------------------------------------------------------------------------
extern "C" void kernel_launch(void* const* d_in, const int* in_sizes, int n_in,
                              void* d_out, int out_size)
{
    (void)in_sizes; (void)n_in; (void)out_size;
    const float* x = (const float*)d_in[0];
    float* out = (float*)d_out;

    cudaFuncSetAttribute(hmma_gemm, cudaFuncAttributeMaxDynamicSharedMemorySize, GEMM_SMEM);

    const float* P[2][9];
    for (int dir = 0; dir < 2; dir++)
        for (int j = 0; j < 9; j++)
            P[dir][j] = (const float*)d_in[1 + dir * 9 + j];

    __half *xhi, *xlo, *xihi, *xilo, *yhi, *ylo, *btin, *btxp, *btout;
    float *p_xz, *p_proj;
    cudaGetSymbolAddress((void**)&xhi, g_xhi);
    cudaGetSymbolAddress((void**)&xlo, g_xlo);
    cudaGetSymbolAddress((void**)&xihi, g_xihi);
    cudaGetSymbolAddress((void**)&xilo, g_xilo);
    cudaGetSymbolAddress((void**)&yhi, g_yhi);
    cudaGetSymbolAddress((void**)&ylo, g_ylo);
    cudaGetSymbolAddress((void**)&btin, g_btin);
    cudaGetSymbolAddress((void**)&btxp, g_btxp);
    cudaGetSymbolAddress((void**)&btout, g_btout);
    cudaGetSymbolAddress((void**)&p_xz, g_xz);
    cudaGetSymbolAddress((void**)&p_proj, g_proj);

    // ---- weight prep ----
    transpose_h_kernel<<<dim3(128, 32), dim3(32, 8)>>>(P[0][0], btin, D_MODEL, 0, 4096);
    transpose_h_kernel<<<dim3(128, 32), dim3(32, 8)>>>(
        P[1][0], btin + (size_t)4096 * D_MODEL, D_MODEL, 0, 4096);
    for (int dir = 0; dir < 2; dir++)
        transpose_h_kernel<<<dim3(4, 64), dim3(32, 8)>>>(
            P[dir][3], btxp + (size_t)dir * 128 * E_DIM, E_DIM, 0, PROJ_N);
    transpose_h_kernel<<<dim3(32, 64), dim3(32, 8)>>>(P[0][8], btout, FOUR_E, 0, D_MODEL);
    transpose_h_kernel<<<dim3(32, 64), dim3(32, 8)>>>(P[1][8], btout, FOUR_E, 2048, D_MODEL);

    // ---- split x ----
    {
        size_t n4 = (size_t)M_ROWS * D_MODEL / 4;
        split_rows_kernel<<<(unsigned)((n4 + 255) / 256), 256>>>(x, xhi, xlo, n4);
    }

    // 1) xz = x @ [in_w_f | in_w_b]
    hmma_gemm<<<dim3(EIGHT_E / 128, M_ROWS / 128, 1), 256, GEMM_SMEM>>>(
        xhi, xlo, btin, p_xz, D_MODEL, D_MODEL, EIGHT_E, 0, 0, 0);

    // 2) conv + silu, both dirs
    {
        size_t n = (size_t)M_ROWS * FOUR_E;
        conv_silu_kernel<<<(unsigned)((n + 255) / 256), 256>>>(
            P[0][1], P[0][2], P[1][1], P[1][2]);
    }

    // 3) proj: both dirs batched via blockIdx.z
    hmma_gemm<<<dim3(1, M_ROWS / 128, 2), 256, GEMM_SMEM>>>(
        xihi, xilo, btxp, p_proj, FOUR_E, E_DIM, PROJ_N,
        (size_t)E_DIM, (size_t)128 * E_DIM, (size_t)M_ROWS * PROJ_N);

    // 4) delta (both dirs)
    delta_kernel<<<dim3(2, M_ROWS / 16, 2), 256>>>(P[0][4], P[0][5], P[1][4], P[1][5]);

    // 5) selective scan (both dirs): 16384 chains, 8 chains/warp
    scan_kernel<<<256, 256>>>(P[0][6], P[1][6]);

    // 6) gate/combine (both dirs)
    {
        size_t n = (size_t)M_ROWS * FOUR_E;
        combine_kernel<<<(unsigned)((n + 255) / 256), 256>>>(P[0][7], P[1][7]);
    }

    // 7) out = [y_f | y_b] @ [out_w_f ; out_w_b]
    hmma_gemm<<<dim3(D_MODEL / 128, M_ROWS / 128, 1), 256, GEMM_SMEM>>>(
        yhi, ylo, btout, out, FOUR_E, FOUR_E, D_MODEL, 0, 0, 0);
}